// round 12
// baseline (speedup 1.0000x reference)
#include <cuda_runtime.h>
#include <cuda_bf16.h>
#include <stdint.h>

// Problem constants (fixed by setup_inputs)
#define NQ   6400
#define CAMS 6
#define LTOT 7979
#define CH   256
#define DFFN 1024
#define NFUS 384   // fused off(256) + attn-logits(128)
#define MVAL (CAMS * LTOT)   // 47874
#define MPAD 48000           // 375 * 128

typedef unsigned long long u64;

// ---------------- scratch (static device globals; no allocation) ----------------
__device__ __nv_bfloat16 g_val_h[MPAD * CH];        // value in bf16 (padded rows stay 0)
__device__ __nv_bfloat16 g_Wval_h[CH * CH];         // W_value bf16
__device__ __nv_bfloat16 g_vproj[MPAD * CH];        // value @ W_value + b (bf16)
__device__ __nv_bfloat16 g_q_h[NQ * CH];            // query in bf16
__device__ __nv_bfloat16 g_Wf_h[CH * NFUS];         // fused [W_off | W_attn] bf16
__device__ float g_bf[NFUS];                        // fused bias (fp32)
__device__ __nv_bfloat16 g_Wout_h[CH * CH];         // W_out bf16
__device__ __nv_bfloat16 g_W1_h[CH * DFFN];         // W1 bf16
__device__ __nv_bfloat16 g_W2_h[DFFN * CH];         // W2 bf16
__device__ float g_fused[NQ * NFUS];                // fused offsets + attn logits
__device__ __nv_bfloat16 g_aggh[NQ * CH];           // aggregated samples (bf16)
__device__ float g_proj[NQ * CH];                   // agg @ W_out
__device__ float g_x[NQ * CH];                      // after LN1 (fp32)
__device__ __nv_bfloat16 g_x_h[NQ * CH];            // after LN1 (bf16)
__device__ __nv_bfloat16 g_ffn1h[NQ * DFFN];        // relu(x@W1+b1) (bf16)
__device__ float g_ffn2[NQ * CH];                   // ffn1@W2+b2
__device__ unsigned int g_vis[NQ];                  // camera visibility bitmask
__device__ float g_cnt[NQ];                         // number of visible cameras

__constant__ int c_W[4] = {100, 50, 25, 13};
__constant__ int c_H[4] = {60, 30, 15, 8};
__constant__ int c_S[4] = {0, 6000, 7500, 7875};

// ---------------- f32x2 packed-math helpers ----------------
__device__ __forceinline__ u64 pkf2(float lo, float hi) {
    u64 r; asm("mov.b64 %0, {%1, %2};" : "=l"(r) : "f"(lo), "f"(hi)); return r;
}
__device__ __forceinline__ u64 bf2f2(uint32_t v) {
    uint32_t lo = v << 16, hi = v & 0xFFFF0000u;
    u64 r; asm("mov.b64 %0, {%1, %2};" : "=l"(r) : "r"(lo), "r"(hi)); return r;
}
__device__ __forceinline__ void ffma2(u64& d, u64 a, u64 b) {
    asm("fma.rn.f32x2 %0, %1, %2, %0;" : "+l"(d) : "l"(a), "l"(b));
}
__device__ __forceinline__ float2 upk(u64 v) {
    float2 f; asm("mov.b64 {%0, %1}, %2;" : "=f"(f.x), "=f"(f.y) : "l"(v)); return f;
}

// ---------------- fused prep: mask + query/weight fp32->bf16 ----------------
__global__ __launch_bounds__(256) void prep_kernel(
    const int* __restrict__ bev, const float* __restrict__ query,
    const float* __restrict__ Woff, const float* __restrict__ Wattn,
    const float* __restrict__ boff, const float* __restrict__ battn,
    const float* __restrict__ Wout, const float* __restrict__ W1,
    const float* __restrict__ W2)
{
    const int b = blockIdx.x, tid = threadIdx.x;
    if (b < 25) {
        int n = b * 256 + tid;
        unsigned int vm = 0; int cnt = 0;
        #pragma unroll
        for (int k = 0; k < CAMS; k++) {
            const int* bp = bev + ((size_t)k * NQ + n) * 4;
            if (bp[0] + bp[1] + bp[2] + bp[3] > 0) { vm |= (1u << k); cnt++; }
        }
        g_vis[n] = vm;
        g_cnt[n] = (float)cnt;
    } else if (b < 1625) {
        int i = (b - 25) * 256 + tid;           // float4 index, < 409600
        float4 v = ((const float4*)query)[i];
        ((__nv_bfloat162*)g_q_h)[i * 2]     = __floats2bfloat162_rn(v.x, v.y);
        ((__nv_bfloat162*)g_q_h)[i * 2 + 1] = __floats2bfloat162_rn(v.z, v.w);
    } else if (b < 2009) {
        int i = (b - 1625) * 256 + tid;         // < 98304
        int k = i / NFUS, n = i % NFUS;
        float v = (n < 256) ? Woff[k * 256 + n] : Wattn[k * 128 + (n - 256)];
        g_Wf_h[i] = __float2bfloat16_rn(v);
        if (i < NFUS) g_bf[i] = (i < 256) ? boff[i] : battn[i - 256];
    } else if (b < 2073) {
        int i = (b - 2009) * 256 + tid;         // < 16384
        float4 v = ((const float4*)Wout)[i];
        ((__nv_bfloat162*)g_Wout_h)[i * 2]     = __floats2bfloat162_rn(v.x, v.y);
        ((__nv_bfloat162*)g_Wout_h)[i * 2 + 1] = __floats2bfloat162_rn(v.z, v.w);
    } else if (b < 2329) {
        int i = (b - 2073) * 256 + tid;         // < 65536
        float4 v = ((const float4*)W1)[i];
        ((__nv_bfloat162*)g_W1_h)[i * 2]     = __floats2bfloat162_rn(v.x, v.y);
        ((__nv_bfloat162*)g_W1_h)[i * 2 + 1] = __floats2bfloat162_rn(v.z, v.w);
    } else {
        int i = (b - 2329) * 256 + tid;         // < 65536
        float4 v = ((const float4*)W2)[i];
        ((__nv_bfloat162*)g_W2_h)[i * 2]     = __floats2bfloat162_rn(v.x, v.y);
        ((__nv_bfloat162*)g_W2_h)[i * 2 + 1] = __floats2bfloat162_rn(v.z, v.w);
    }
}

// ---------------- value + W_value fp32 -> bf16 (stream 2) ----------------
__global__ __launch_bounds__(256) void conv_val_kernel(
    const float* __restrict__ val, const float* __restrict__ Wv)
{
    const int NV = MVAL * CH / 4;   // 3,063,936
    int i = blockIdx.x * 256 + threadIdx.x;
    if (i < NV) {
        float4 v = ((const float4*)val)[i];
        ((__nv_bfloat162*)g_val_h)[i * 2]     = __floats2bfloat162_rn(v.x, v.y);
        ((__nv_bfloat162*)g_val_h)[i * 2 + 1] = __floats2bfloat162_rn(v.z, v.w);
    } else {
        int j = i - NV;
        if (j < CH * CH / 4) {
            float4 v = ((const float4*)Wv)[j];
            ((__nv_bfloat162*)g_Wval_h)[j * 2]     = __floats2bfloat162_rn(v.x, v.y);
            ((__nv_bfloat162*)g_Wval_h)[j * 2 + 1] = __floats2bfloat162_rn(v.z, v.w);
        }
    }
}

// ---------------- tensor-core GEMM building blocks ----------------
__device__ __forceinline__ void ldsm4(uint32_t* r, const void* p) {
    uint32_t a = (uint32_t)__cvta_generic_to_shared(p);
    asm volatile("ldmatrix.sync.aligned.m8n8.x4.shared.b16 {%0,%1,%2,%3}, [%4];"
                 : "=r"(r[0]), "=r"(r[1]), "=r"(r[2]), "=r"(r[3]) : "r"(a));
}
__device__ __forceinline__ void ldsm4t(uint32_t* r, const void* p) {
    uint32_t a = (uint32_t)__cvta_generic_to_shared(p);
    asm volatile("ldmatrix.sync.aligned.m8n8.x4.trans.shared.b16 {%0,%1,%2,%3}, [%4];"
                 : "=r"(r[0]), "=r"(r[1]), "=r"(r[2]), "=r"(r[3]) : "r"(a));
}
__device__ __forceinline__ void mma_bf16(float* d, const uint32_t* a, const uint32_t* b) {
    asm volatile("mma.sync.aligned.m16n8k16.row.col.f32.bf16.bf16.f32 "
                 "{%0,%1,%2,%3}, {%4,%5,%6,%7}, {%8,%9}, {%0,%1,%2,%3};"
                 : "+f"(d[0]), "+f"(d[1]), "+f"(d[2]), "+f"(d[3])
                 : "r"(a[0]), "r"(a[1]), "r"(a[2]), "r"(a[3]), "r"(b[0]), "r"(b[1]));
}
__device__ __forceinline__ void cpa16(void* dst, const void* src) {
    uint32_t d = (uint32_t)__cvta_generic_to_shared(dst);
    asm volatile("cp.async.cg.shared.global [%0], [%1], 16;" :: "r"(d), "l"(src));
}
__device__ __forceinline__ void store2(float* C, float x, float y) {
    *(float2*)C = make_float2(x, y);
}
__device__ __forceinline__ void store2(__nv_bfloat16* C, float x, float y) {
    *(__nv_bfloat162*)C = __floats2bfloat162_rn(x, y);
}

// ================== bf16 cp.async GEMM ==================
// C(MxN) = A(MxK,bf16 rm) * B(KxN,bf16 rm) (+bias)(+relu). 128x64 tile, BK=32,
// 4-stage cp.async, 256 thr (8 warps x 32x32). M%128==0, N%64==0, K%32==0.
#define STAGES 4
template<int EPI, typename OutT>
__global__ __launch_bounds__(256, 2) void hgemm_bf16(
    const __nv_bfloat16* __restrict__ A, const __nv_bfloat16* __restrict__ B,
    const float* __restrict__ bias, OutT* __restrict__ C,
    int M, int N, int K)
{
    __shared__ __align__(16) __nv_bfloat16 As[STAGES][128][40];
    __shared__ __align__(16) __nv_bfloat16 Bs[STAGES][32][72];   // [k][n]
    const int tid = threadIdx.x;
    const int bm = blockIdx.x * 128, bn = blockIdx.y * 64;
    const int lane = tid & 31, w = tid >> 5;
    const int m0 = (w >> 1) * 32, n0 = (w & 1) * 32;

    float acc[2][4][4];
    #pragma unroll
    for (int i = 0; i < 2; i++)
        #pragma unroll
        for (int j = 0; j < 4; j++)
            #pragma unroll
            for (int l = 0; l < 4; l++) acc[i][j][l] = 0.0f;

    const int arow = tid >> 1, acol = (tid & 1) * 16;
    const int brow = tid >> 3, bcol = (tid & 7) * 8;

    const __nv_bfloat16* Asrc = A + (size_t)(bm + arow) * K + acol;
    const __nv_bfloat16* Bsrc = B + bn + bcol;

    const int KT = K >> 5;

#define ISSUE(s, kt) do {                                                      \
    cpa16(&As[s][arow][acol],     Asrc + (kt) * 32);                           \
    cpa16(&As[s][arow][acol + 8], Asrc + (kt) * 32 + 8);                       \
    cpa16(&Bs[s][brow][bcol],     Bsrc + (size_t)((kt) * 32 + brow) * N);      \
} while (0)

#define COMPUTE_T(b) do {                                                      \
    _Pragma("unroll")                                                          \
    for (int ks = 0; ks < 2; ks++) {                                           \
        uint32_t af[2][4], bfr[4][2];                                          \
        _Pragma("unroll")                                                      \
        for (int mt = 0; mt < 2; mt++)                                         \
            ldsm4(af[mt], &As[b][m0 + mt * 16 + (lane & 15)]                   \
                             [ks * 16 + ((lane >> 4) << 3)]);                  \
        _Pragma("unroll")                                                      \
        for (int nt2 = 0; nt2 < 2; nt2++) {                                    \
            uint32_t t[4];                                                     \
            ldsm4t(t, &Bs[b][ks * 16 + (lane & 7) + 8 * ((lane >> 3) & 1)]     \
                            [n0 + nt2 * 16 + 8 * (lane >> 4)]);                \
            bfr[nt2 * 2][0] = t[0];      bfr[nt2 * 2][1] = t[1];               \
            bfr[nt2 * 2 + 1][0] = t[2];  bfr[nt2 * 2 + 1][1] = t[3];           \
        }                                                                      \
        _Pragma("unroll")                                                      \
        for (int mt = 0; mt < 2; mt++)                                         \
            _Pragma("unroll")                                                  \
            for (int nt = 0; nt < 4; nt++)                                     \
                mma_bf16(acc[mt][nt], af[mt], bfr[nt]);                        \
    }                                                                          \
} while (0)

    #pragma unroll
    for (int s = 0; s < STAGES - 1; s++) {
        if (s < KT) ISSUE(s, s);
        asm volatile("cp.async.commit_group;");
    }

    for (int kt = 0; kt < KT; kt++) {
        asm volatile("cp.async.wait_group %0;" :: "n"(STAGES - 2));
        __syncthreads();
        int kn = kt + STAGES - 1;
        if (kn < KT) ISSUE(kn & (STAGES - 1), kn);
        asm volatile("cp.async.commit_group;");
        COMPUTE_T(kt & (STAGES - 1));
    }
#undef ISSUE
#undef COMPUTE_T

    const int row0 = bm + m0 + (lane >> 2);
    #pragma unroll
    for (int mt = 0; mt < 2; mt++) {
        int r0 = row0 + mt * 16, r1 = r0 + 8;
        #pragma unroll
        for (int nt = 0; nt < 4; nt++) {
            int col = bn + n0 + nt * 8 + ((lane & 3) << 1);
            float b0 = 0.f, b1 = 0.f;
            if (EPI >= 1) { b0 = __ldg(bias + col); b1 = __ldg(bias + col + 1); }
            float v0 = acc[mt][nt][0] + b0, v1 = acc[mt][nt][1] + b1;
            float v2 = acc[mt][nt][2] + b0, v3 = acc[mt][nt][3] + b1;
            if (EPI == 2) {
                v0 = fmaxf(v0, 0.f); v1 = fmaxf(v1, 0.f);
                v2 = fmaxf(v2, 0.f); v3 = fmaxf(v3, 0.f);
            }
            store2(C + (size_t)r0 * N + col, v0, v1);
            store2(C + (size_t)r1 * N + col, v2, v3);
        }
    }
}

// ---------------- deformable sampling + cross-camera aggregation ----------------
// Block = one query. Phase 0: fused softmax. Phase 1: 768 combos -> weights
// pre-duplicated as f32x2 (u64) + precomputed byte offsets. Phase 2: thread
// (cg = tid&31 -> 8 channels, pgrp = tid>>5 -> 2 of 16 points): per corner one
// pointer add + LDG.128, bf16x2 unpack, packed FMA.
__global__ __launch_bounds__(256) void sample_kernel(
    const float* __restrict__ ref)   // (6, 6400, 4, 2)
{
    __shared__ __align__(16) u64 swd[768][4];   // 24 KB: weights duplicated f32x2
    __shared__ int4 sbo[768];                   // 12 KB: corner byte offsets
    __shared__ float saw[128];
    __shared__ float4 sred[256][2];             // 8 KB
    const int n = blockIdx.x;
    const int tid = threadIdx.x;
    const unsigned int vism = g_vis[n];

    // Phase 0: softmax over each 16-point group (8 heads)
    if (tid < 128) {
        float lv = g_fused[(size_t)n * NFUS + 256 + tid];
        float mx = lv;
        #pragma unroll
        for (int o = 8; o > 0; o >>= 1)
            mx = fmaxf(mx, __shfl_xor_sync(0xffffffffu, mx, o));
        float e = expf(lv - mx);
        float s = e;
        #pragma unroll
        for (int o = 8; o > 0; o >>= 1)
            s += __shfl_xor_sync(0xffffffffu, s, o);
        saw[tid] = e / s;
    }
    __syncthreads();

    // Phase 1: weights (duplicated) + corner byte offsets
    #pragma unroll
    for (int t = 0; t < 3; t++) {
        int cid = tid + t * 256;
        int k = cid >> 7;
        int r = cid & 127;          // h*16 + lvl*4 + p
        int h = r >> 4;
        int lvl = (r >> 2) & 3;
        int p = r & 3;
        float4 wv = make_float4(0.f, 0.f, 0.f, 0.f);
        int4 iv = make_int4(0, 0, 0, 0);
        if ((vism >> k) & 1) {
            int Wi = c_W[lvl], Hi = c_H[lvl];
            float Wf = (float)Wi, Hf = (float)Hi;
            const float* rp = ref + (((size_t)k * NQ + n) * 4 + lvl) * 2;
            float rx = rp[0], ry = rp[1];
            int oi = ((h * 4 + lvl) * 4 + p) * 2;
            float ox = g_fused[(size_t)n * NFUS + oi];
            float oy = g_fused[(size_t)n * NFUS + oi + 1];
            float x = (rx + ox / Wf) * Wf - 0.5f;
            float y = (ry + oy / Hf) * Hf - 0.5f;
            float x0f = floorf(x), y0f = floorf(y);
            float lx = x - x0f, ly = y - y0f;
            int x0 = (int)x0f, y0 = (int)y0f;
            float a = saw[r];
            bool vx0 = (x0 >= 0) && (x0 < Wi);
            bool vx1 = (x0 + 1 >= 0) && (x0 + 1 < Wi);
            bool vy0 = (y0 >= 0) && (y0 < Hi);
            bool vy1 = (y0 + 1 >= 0) && (y0 + 1 < Hi);
            float omx = 1.0f - lx, omy = 1.0f - ly;
            wv.x = (vx0 && vy0) ? a * omx * omy : 0.0f;
            wv.y = (vx1 && vy0) ? a * lx * omy : 0.0f;
            wv.z = (vx0 && vy1) ? a * omx * ly : 0.0f;
            wv.w = (vx1 && vy1) ? a * lx * ly : 0.0f;
            int xc0 = min(max(x0, 0), Wi - 1);
            int xc1 = min(max(x0 + 1, 0), Wi - 1);
            int yc0 = min(max(y0, 0), Hi - 1);
            int yc1 = min(max(y0 + 1, 0), Hi - 1);
            int rb = k * LTOT + c_S[lvl];
            int r0 = rb + yc0 * Wi, r1 = rb + yc1 * Wi;
            // byte offset = row * CH * sizeof(bf16) = row * 512
            iv = make_int4((r0 + xc0) << 9, (r0 + xc1) << 9,
                           (r1 + xc0) << 9, (r1 + xc1) << 9);
        }
        swd[cid][0] = pkf2(wv.x, wv.x);
        swd[cid][1] = pkf2(wv.y, wv.y);
        swd[cid][2] = pkf2(wv.z, wv.z);
        swd[cid][3] = pkf2(wv.w, wv.w);
        sbo[cid] = iv;
    }
    __syncthreads();

    // Phase 2: gather + packed FMA
    const int cg = tid & 31;              // 8-channel group
    const int hh = cg >> 2;               // head
    const int pgrp = tid >> 5;            // handles points {2*pgrp, 2*pgrp+1}
    const char* vbb = (const char*)g_vproj + cg * 16;
    u64 a0 = 0, a1 = 0, a2 = 0, a3 = 0;

    #pragma unroll 1
    for (int k = 0; k < CAMS; k++) {
        if (!((vism >> k) & 1)) continue;
        const int base = k * 128 + hh * 16 + pgrp * 2;
        #pragma unroll
        for (int j = 0; j < 2; j++) {
            const u64* wp = swd[base + j];
            u64 w0 = wp[0], w1 = wp[1], w2 = wp[2], w3 = wp[3];
            int4 bo = sbo[base + j];
            uint4 q0 = *(const uint4*)(vbb + bo.x);
            uint4 q1 = *(const uint4*)(vbb + bo.y);
            uint4 q2 = *(const uint4*)(vbb + bo.z);
            uint4 q3 = *(const uint4*)(vbb + bo.w);
            ffma2(a0, w0, bf2f2(q0.x)); ffma2(a1, w0, bf2f2(q0.y));
            ffma2(a2, w0, bf2f2(q0.z)); ffma2(a3, w0, bf2f2(q0.w));
            ffma2(a0, w1, bf2f2(q1.x)); ffma2(a1, w1, bf2f2(q1.y));
            ffma2(a2, w1, bf2f2(q1.z)); ffma2(a3, w1, bf2f2(q1.w));
            ffma2(a0, w2, bf2f2(q2.x)); ffma2(a1, w2, bf2f2(q2.y));
            ffma2(a2, w2, bf2f2(q2.z)); ffma2(a3, w2, bf2f2(q2.w));
            ffma2(a0, w3, bf2f2(q3.x)); ffma2(a1, w3, bf2f2(q3.y));
            ffma2(a2, w3, bf2f2(q3.z)); ffma2(a3, w3, bf2f2(q3.w));
        }
    }

    float2 f0 = upk(a0), f1 = upk(a1), f2 = upk(a2), f3 = upk(a3);
    sred[tid][0] = make_float4(f0.x, f0.y, f1.x, f1.y);
    sred[tid][1] = make_float4(f2.x, f2.y, f3.x, f3.y);
    __syncthreads();
    if (tid < 128) {
        float4 x0 = sred[tid + 128][0], x1 = sred[tid + 128][1];
        float4 y0 = sred[tid][0], y1 = sred[tid][1];
        y0.x += x0.x; y0.y += x0.y; y0.z += x0.z; y0.w += x0.w;
        y1.x += x1.x; y1.y += x1.y; y1.z += x1.z; y1.w += x1.w;
        sred[tid][0] = y0; sred[tid][1] = y1;
    }
    __syncthreads();
    if (tid < 64) {
        float4 x0 = sred[tid + 64][0], x1 = sred[tid + 64][1];
        float4 y0 = sred[tid][0], y1 = sred[tid][1];
        y0.x += x0.x; y0.y += x0.y; y0.z += x0.z; y0.w += x0.w;
        y1.x += x1.x; y1.y += x1.y; y1.z += x1.z; y1.w += x1.w;
        sred[tid][0] = y0; sred[tid][1] = y1;
    }
    __syncthreads();
    if (tid < 32) {
        float4 x0 = sred[tid + 32][0], x1 = sred[tid + 32][1];
        float4 y0 = sred[tid][0], y1 = sred[tid][1];
        y0.x += x0.x; y0.y += x0.y; y0.z += x0.z; y0.w += x0.w;
        y1.x += x1.x; y1.y += x1.y; y1.z += x1.z; y1.w += x1.w;
        __nv_bfloat162 p0 = __floats2bfloat162_rn(y0.x, y0.y);
        __nv_bfloat162 p1 = __floats2bfloat162_rn(y0.z, y0.w);
        __nv_bfloat162 p2 = __floats2bfloat162_rn(y1.x, y1.y);
        __nv_bfloat162 p3 = __floats2bfloat162_rn(y1.z, y1.w);
        uint4 pk;
        pk.x = *(uint32_t*)&p0; pk.y = *(uint32_t*)&p1;
        pk.z = *(uint32_t*)&p2; pk.w = *(uint32_t*)&p3;
        *(uint4*)(g_aggh + (size_t)n * CH + tid * 8) = pk;
    }
}

// ---------------- block reduction helper ----------------
__device__ __forceinline__ float blocksum256(float v, float* sh) {
    #pragma unroll
    for (int o = 16; o > 0; o >>= 1) v += __shfl_xor_sync(0xffffffffu, v, o);
    if ((threadIdx.x & 31) == 0) sh[threadIdx.x >> 5] = v;
    __syncthreads();
    float s = 0.f;
    #pragma unroll
    for (int i = 0; i < 8; i++) s += sh[i];
    __syncthreads();
    return s;
}

// ---------------- slots assembly + residual + LN1 ----------------
__global__ __launch_bounds__(256) void ln1_kernel(
    const float* __restrict__ query, const float* __restrict__ b_out,
    const float* __restrict__ gamma, const float* __restrict__ beta)
{
    __shared__ float sh[8];
    const int n = blockIdx.x, c = threadIdx.x;
    float m = g_cnt[n];
    float q = query[(size_t)n * CH + c];
    float s = m * (q + b_out[c]) + g_proj[(size_t)n * CH + c];
    float t = s / fmaxf(m, 1.0f) + q;
    float mu = blocksum256(t, sh) * (1.0f / CH);
    float d = t - mu;
    float var = blocksum256(d * d, sh) * (1.0f / CH);
    float xv = d * rsqrtf(var + 1e-5f) * gamma[c] + beta[c];
    g_x[(size_t)n * CH + c] = xv;
    g_x_h[(size_t)n * CH + c] = __float2bfloat16_rn(xv);
}

// ---------------- FFN residual + LN2 -> output ----------------
__global__ __launch_bounds__(256) void ln2_kernel(
    const float* __restrict__ gamma, const float* __restrict__ beta,
    float* __restrict__ out)
{
    __shared__ float sh[8];
    const int n = blockIdx.x, c = threadIdx.x;
    float t = g_x[(size_t)n * CH + c] + g_ffn2[(size_t)n * CH + c];
    float mu = blocksum256(t, sh) * (1.0f / CH);
    float d = t - mu;
    float var = blocksum256(d * d, sh) * (1.0f / CH);
    out[(size_t)n * CH + c] = d * rsqrtf(var + 1e-5f) * gamma[c] + beta[c];
}

// ---------------- host launcher ----------------
extern "C" void kernel_launch(void* const* d_in, const int* in_sizes, int n_in,
                              void* d_out, int out_size) {
    const float* query   = (const float*)d_in[0];
    const float* value   = (const float*)d_in[2];
    const float* refpts  = (const float*)d_in[3];
    const int*   bev     = (const int*)d_in[6];
    const float* W_value = (const float*)d_in[7];
    const float* b_value = (const float*)d_in[8];
    const float* W_off   = (const float*)d_in[9];
    const float* b_off   = (const float*)d_in[10];
    const float* W_attn  = (const float*)d_in[11];
    const float* b_attn  = (const float*)d_in[12];
    const float* W_out   = (const float*)d_in[13];
    const float* b_out   = (const float*)d_in[14];
    const float* ln1_g   = (const float*)d_in[15];
    const float* ln1_b   = (const float*)d_in[16];
    const float* W1      = (const float*)d_in[17];
    const float* b1      = (const float*)d_in[18];
    const float* W2      = (const float*)d_in[19];
    const float* b2      = (const float*)d_in[20];
    const float* ln2_g   = (const float*)d_in[21];
    const float* ln2_b   = (const float*)d_in[22];
    float* out = (float*)d_out;

    void *p_valh, *p_Wvalh, *p_vproj, *p_qh, *p_Wfh, *p_bf, *p_Wouth, *p_W1h, *p_W2h;
    void *p_fused, *p_aggh, *p_proj, *p_xh, *p_ffn1h, *p_ffn2;
    cudaGetSymbolAddress(&p_valh,   g_val_h);
    cudaGetSymbolAddress(&p_Wvalh,  g_Wval_h);
    cudaGetSymbolAddress(&p_vproj,  g_vproj);
    cudaGetSymbolAddress(&p_qh,     g_q_h);
    cudaGetSymbolAddress(&p_Wfh,    g_Wf_h);
    cudaGetSymbolAddress(&p_bf,     g_bf);
    cudaGetSymbolAddress(&p_Wouth,  g_Wout_h);
    cudaGetSymbolAddress(&p_W1h,    g_W1_h);
    cudaGetSymbolAddress(&p_W2h,    g_W2_h);
    cudaGetSymbolAddress(&p_fused,  g_fused);
    cudaGetSymbolAddress(&p_aggh,   g_aggh);
    cudaGetSymbolAddress(&p_proj,   g_proj);
    cudaGetSymbolAddress(&p_xh,     g_x_h);
    cudaGetSymbolAddress(&p_ffn1h,  g_ffn1h);
    cudaGetSymbolAddress(&p_ffn2,   g_ffn2);

    static cudaStream_t s2 = nullptr;
    static cudaEvent_t ev_fork = nullptr, ev_join = nullptr;
    if (s2 == nullptr) {
        cudaStreamCreateWithFlags(&s2, cudaStreamNonBlocking);
        cudaEventCreateWithFlags(&ev_fork, cudaEventDisableTiming);
        cudaEventCreateWithFlags(&ev_join, cudaEventDisableTiming);
    }

    // ---- fork: value/W_value conversion + vproj GEMM (bf16 out) on s2 ----
    cudaEventRecord(ev_fork, 0);
    cudaStreamWaitEvent(s2, ev_fork, 0);
    {
        int nconv = (MVAL * CH / 4 + CH * CH / 4 + 255) / 256;
        conv_val_kernel<<<nconv, 256, 0, s2>>>(value, W_value);
        hgemm_bf16<1, __nv_bfloat16><<<dim3(MPAD / 128, CH / 64), 256, 0, s2>>>(
            (const __nv_bfloat16*)p_valh, (const __nv_bfloat16*)p_Wvalh,
            b_value, (__nv_bfloat16*)p_vproj, MPAD, CH, CH);
    }
    cudaEventRecord(ev_join, s2);

    // ---- main stream: prep + fused off/attn GEMM ----
    prep_kernel<<<2585, 256>>>(bev, query, W_off, W_attn, b_off, b_attn,
                               W_out, W1, W2);
    hgemm_bf16<1, float><<<dim3(NQ / 128, NFUS / 64), 256>>>(
        (const __nv_bfloat16*)p_qh, (const __nv_bfloat16*)p_Wfh,
        (const float*)p_bf, (float*)p_fused, NQ, NFUS, CH);

    // ---- join, then sampling ----
    cudaStreamWaitEvent(0, ev_join, 0);
    sample_kernel<<<NQ, 256>>>(refpts);

    // output projection: agg(bf16) @ W_out (bias folded into ln1)
    hgemm_bf16<0, float><<<dim3(NQ / 128, CH / 64), 256>>>(
        (const __nv_bfloat16*)p_aggh, (const __nv_bfloat16*)p_Wouth,
        nullptr, (float*)p_proj, NQ, CH, CH);

    // slots + residual + LN1
    ln1_kernel<<<NQ, 256>>>(query, b_out, ln1_g, ln1_b);

    // FFN up: relu(x @ W1 + b1) -> bf16
    hgemm_bf16<2, __nv_bfloat16><<<dim3(NQ / 128, DFFN / 64), 256>>>(
        (const __nv_bfloat16*)p_xh, (const __nv_bfloat16*)p_W1h,
        b1, (__nv_bfloat16*)p_ffn1h, NQ, DFFN, CH);

    // FFN down: ffn1(bf16) @ W2 + b2
    hgemm_bf16<1, float><<<dim3(NQ / 128, CH / 64), 256>>>(
        (const __nv_bfloat16*)p_ffn1h, (const __nv_bfloat16*)p_W2h,
        b2, (float*)p_ffn2, NQ, CH, DFFN);

    // residual + LN2 -> out
    ln2_kernel<<<NQ, 256>>>(ln2_g, ln2_b, out);

    (void)in_sizes; (void)n_in; (void)out_size;
}

// round 13
// speedup vs baseline: 1.0377x; 1.0377x over previous
#include <cuda_runtime.h>
#include <cuda_bf16.h>
#include <stdint.h>

// Problem constants (fixed by setup_inputs)
#define NQ   6400
#define CAMS 6
#define LTOT 7979
#define CH   256
#define DFFN 1024
#define NFUS 384   // fused off(256) + attn-logits(128)
#define MVAL (CAMS * LTOT)   // 47874

typedef unsigned long long u64;

// ---------------- scratch (static device globals; no allocation) ----------------
__device__ __nv_bfloat16 g_vproj[MVAL * CH];        // value @ W_value + b (bf16)
__device__ __nv_bfloat16 g_q_h[NQ * CH];            // query in bf16
__device__ __nv_bfloat16 g_Wf_h[CH * NFUS];         // fused [W_off | W_attn] bf16
__device__ float g_bf[NFUS];                        // fused bias (fp32)
__device__ __nv_bfloat16 g_Wout_h[CH * CH];         // W_out bf16
__device__ __nv_bfloat16 g_W1_h[CH * DFFN];         // W1 bf16
__device__ __nv_bfloat16 g_W2_h[DFFN * CH];         // W2 bf16
__device__ float g_fused[NQ * NFUS];                // fused offsets + attn logits
__device__ __nv_bfloat16 g_aggh[NQ * CH];           // aggregated samples (bf16)
__device__ float g_proj[NQ * CH];                   // agg @ W_out
__device__ float g_x[NQ * CH];                      // after LN1 (fp32)
__device__ __nv_bfloat16 g_x_h[NQ * CH];            // after LN1 (bf16)
__device__ __nv_bfloat16 g_ffn1h[NQ * DFFN];        // relu(x@W1+b1) (bf16)
__device__ float g_ffn2[NQ * CH];                   // ffn1@W2+b2
__device__ unsigned int g_vis[NQ];                  // camera visibility bitmask
__device__ float g_cnt[NQ];                         // number of visible cameras

__constant__ int c_W[4] = {100, 50, 25, 13};
__constant__ int c_H[4] = {60, 30, 15, 8};
__constant__ int c_S[4] = {0, 6000, 7500, 7875};

// ---------------- f32x2 packed-math helpers ----------------
__device__ __forceinline__ u64 pkf2(float lo, float hi) {
    u64 r; asm("mov.b64 %0, {%1, %2};" : "=l"(r) : "f"(lo), "f"(hi)); return r;
}
__device__ __forceinline__ u64 bf2f2(uint32_t v) {
    uint32_t lo = v << 16, hi = v & 0xFFFF0000u;
    u64 r; asm("mov.b64 %0, {%1, %2};" : "=l"(r) : "r"(lo), "r"(hi)); return r;
}
__device__ __forceinline__ void ffma2(u64& d, u64 a, u64 b) {
    asm("fma.rn.f32x2 %0, %1, %2, %0;" : "+l"(d) : "l"(a), "l"(b));
}
__device__ __forceinline__ float2 upk(u64 v) {
    float2 f; asm("mov.b64 {%0, %1}, %2;" : "=f"(f.x), "=f"(f.y) : "l"(v)); return f;
}

// ---------------- fused prep: mask + query/weight fp32->bf16 ----------------
__global__ __launch_bounds__(256) void prep_kernel(
    const int* __restrict__ bev, const float* __restrict__ query,
    const float* __restrict__ Woff, const float* __restrict__ Wattn,
    const float* __restrict__ boff, const float* __restrict__ battn,
    const float* __restrict__ Wout, const float* __restrict__ W1,
    const float* __restrict__ W2)
{
    const int b = blockIdx.x, tid = threadIdx.x;
    if (b < 25) {
        int n = b * 256 + tid;
        unsigned int vm = 0; int cnt = 0;
        #pragma unroll
        for (int k = 0; k < CAMS; k++) {
            const int* bp = bev + ((size_t)k * NQ + n) * 4;
            if (bp[0] + bp[1] + bp[2] + bp[3] > 0) { vm |= (1u << k); cnt++; }
        }
        g_vis[n] = vm;
        g_cnt[n] = (float)cnt;
    } else if (b < 1625) {
        int i = (b - 25) * 256 + tid;           // float4 index, < 409600
        float4 v = ((const float4*)query)[i];
        ((__nv_bfloat162*)g_q_h)[i * 2]     = __floats2bfloat162_rn(v.x, v.y);
        ((__nv_bfloat162*)g_q_h)[i * 2 + 1] = __floats2bfloat162_rn(v.z, v.w);
    } else if (b < 2009) {
        int i = (b - 1625) * 256 + tid;         // < 98304
        int k = i / NFUS, n = i % NFUS;
        float v = (n < 256) ? Woff[k * 256 + n] : Wattn[k * 128 + (n - 256)];
        g_Wf_h[i] = __float2bfloat16_rn(v);
        if (i < NFUS) g_bf[i] = (i < 256) ? boff[i] : battn[i - 256];
    } else if (b < 2073) {
        int i = (b - 2009) * 256 + tid;         // < 16384
        float4 v = ((const float4*)Wout)[i];
        ((__nv_bfloat162*)g_Wout_h)[i * 2]     = __floats2bfloat162_rn(v.x, v.y);
        ((__nv_bfloat162*)g_Wout_h)[i * 2 + 1] = __floats2bfloat162_rn(v.z, v.w);
    } else if (b < 2329) {
        int i = (b - 2073) * 256 + tid;         // < 65536
        float4 v = ((const float4*)W1)[i];
        ((__nv_bfloat162*)g_W1_h)[i * 2]     = __floats2bfloat162_rn(v.x, v.y);
        ((__nv_bfloat162*)g_W1_h)[i * 2 + 1] = __floats2bfloat162_rn(v.z, v.w);
    } else {
        int i = (b - 2329) * 256 + tid;         // < 65536
        float4 v = ((const float4*)W2)[i];
        ((__nv_bfloat162*)g_W2_h)[i * 2]     = __floats2bfloat162_rn(v.x, v.y);
        ((__nv_bfloat162*)g_W2_h)[i * 2 + 1] = __floats2bfloat162_rn(v.z, v.w);
    }
}

// ---------------- tensor-core GEMM building blocks ----------------
__device__ __forceinline__ void ldsm4(uint32_t* r, const void* p) {
    uint32_t a = (uint32_t)__cvta_generic_to_shared(p);
    asm volatile("ldmatrix.sync.aligned.m8n8.x4.shared.b16 {%0,%1,%2,%3}, [%4];"
                 : "=r"(r[0]), "=r"(r[1]), "=r"(r[2]), "=r"(r[3]) : "r"(a));
}
__device__ __forceinline__ void ldsm4t(uint32_t* r, const void* p) {
    uint32_t a = (uint32_t)__cvta_generic_to_shared(p);
    asm volatile("ldmatrix.sync.aligned.m8n8.x4.trans.shared.b16 {%0,%1,%2,%3}, [%4];"
                 : "=r"(r[0]), "=r"(r[1]), "=r"(r[2]), "=r"(r[3]) : "r"(a));
}
__device__ __forceinline__ void mma_bf16(float* d, const uint32_t* a, const uint32_t* b) {
    asm volatile("mma.sync.aligned.m16n8k16.row.col.f32.bf16.bf16.f32 "
                 "{%0,%1,%2,%3}, {%4,%5,%6,%7}, {%8,%9}, {%0,%1,%2,%3};"
                 : "+f"(d[0]), "+f"(d[1]), "+f"(d[2]), "+f"(d[3])
                 : "r"(a[0]), "r"(a[1]), "r"(a[2]), "r"(a[3]), "r"(b[0]), "r"(b[1]));
}
__device__ __forceinline__ void cpa16(void* dst, const void* src) {
    uint32_t d = (uint32_t)__cvta_generic_to_shared(dst);
    asm volatile("cp.async.cg.shared.global [%0], [%1], 16;" :: "r"(d), "l"(src));
}
__device__ __forceinline__ void store2(float* C, float x, float y) {
    *(float2*)C = make_float2(x, y);
}
__device__ __forceinline__ void store2(__nv_bfloat16* C, float x, float y) {
    *(__nv_bfloat162*)C = __floats2bfloat162_rn(x, y);
}

// ================== bf16 cp.async GEMM ==================
// C(MxN) = A(MxK,bf16 rm) * B(KxN,bf16 rm) (+bias)(+relu). 128x64 tile, BK=32,
// 4-stage cp.async, 256 thr (8 warps x 32x32). M%128==0, N%64==0, K%32==0.
#define STAGES 4
template<int EPI, typename OutT>
__global__ __launch_bounds__(256, 2) void hgemm_bf16(
    const __nv_bfloat16* __restrict__ A, const __nv_bfloat16* __restrict__ B,
    const float* __restrict__ bias, OutT* __restrict__ C,
    int M, int N, int K)
{
    __shared__ __align__(16) __nv_bfloat16 As[STAGES][128][40];
    __shared__ __align__(16) __nv_bfloat16 Bs[STAGES][32][72];   // [k][n]
    const int tid = threadIdx.x;
    const int bm = blockIdx.x * 128, bn = blockIdx.y * 64;
    const int lane = tid & 31, w = tid >> 5;
    const int m0 = (w >> 1) * 32, n0 = (w & 1) * 32;

    float acc[2][4][4];
    #pragma unroll
    for (int i = 0; i < 2; i++)
        #pragma unroll
        for (int j = 0; j < 4; j++)
            #pragma unroll
            for (int l = 0; l < 4; l++) acc[i][j][l] = 0.0f;

    const int arow = tid >> 1, acol = (tid & 1) * 16;
    const int brow = tid >> 3, bcol = (tid & 7) * 8;

    const __nv_bfloat16* Asrc = A + (size_t)(bm + arow) * K + acol;
    const __nv_bfloat16* Bsrc = B + bn + bcol;

    const int KT = K >> 5;

#define ISSUE(s, kt) do {                                                      \
    cpa16(&As[s][arow][acol],     Asrc + (kt) * 32);                           \
    cpa16(&As[s][arow][acol + 8], Asrc + (kt) * 32 + 8);                       \
    cpa16(&Bs[s][brow][bcol],     Bsrc + (size_t)((kt) * 32 + brow) * N);      \
} while (0)

#define COMPUTE_T(b) do {                                                      \
    _Pragma("unroll")                                                          \
    for (int ks = 0; ks < 2; ks++) {                                           \
        uint32_t af[2][4], bfr[4][2];                                          \
        _Pragma("unroll")                                                      \
        for (int mt = 0; mt < 2; mt++)                                         \
            ldsm4(af[mt], &As[b][m0 + mt * 16 + (lane & 15)]                   \
                             [ks * 16 + ((lane >> 4) << 3)]);                  \
        _Pragma("unroll")                                                      \
        for (int nt2 = 0; nt2 < 2; nt2++) {                                    \
            uint32_t t[4];                                                     \
            ldsm4t(t, &Bs[b][ks * 16 + (lane & 7) + 8 * ((lane >> 3) & 1)]     \
                            [n0 + nt2 * 16 + 8 * (lane >> 4)]);                \
            bfr[nt2 * 2][0] = t[0];      bfr[nt2 * 2][1] = t[1];               \
            bfr[nt2 * 2 + 1][0] = t[2];  bfr[nt2 * 2 + 1][1] = t[3];           \
        }                                                                      \
        _Pragma("unroll")                                                      \
        for (int mt = 0; mt < 2; mt++)                                         \
            _Pragma("unroll")                                                  \
            for (int nt = 0; nt < 4; nt++)                                     \
                mma_bf16(acc[mt][nt], af[mt], bfr[nt]);                        \
    }                                                                          \
} while (0)

    #pragma unroll
    for (int s = 0; s < STAGES - 1; s++) {
        if (s < KT) ISSUE(s, s);
        asm volatile("cp.async.commit_group;");
    }

    for (int kt = 0; kt < KT; kt++) {
        asm volatile("cp.async.wait_group %0;" :: "n"(STAGES - 2));
        __syncthreads();
        int kn = kt + STAGES - 1;
        if (kn < KT) ISSUE(kn & (STAGES - 1), kn);
        asm volatile("cp.async.commit_group;");
        COMPUTE_T(kt & (STAGES - 1));
    }
#undef ISSUE
#undef COMPUTE_T

    const int row0 = bm + m0 + (lane >> 2);
    #pragma unroll
    for (int mt = 0; mt < 2; mt++) {
        int r0 = row0 + mt * 16, r1 = r0 + 8;
        #pragma unroll
        for (int nt = 0; nt < 4; nt++) {
            int col = bn + n0 + nt * 8 + ((lane & 3) << 1);
            float b0 = 0.f, b1 = 0.f;
            if (EPI >= 1) { b0 = __ldg(bias + col); b1 = __ldg(bias + col + 1); }
            float v0 = acc[mt][nt][0] + b0, v1 = acc[mt][nt][1] + b1;
            float v2 = acc[mt][nt][2] + b0, v3 = acc[mt][nt][3] + b1;
            if (EPI == 2) {
                v0 = fmaxf(v0, 0.f); v1 = fmaxf(v1, 0.f);
                v2 = fmaxf(v2, 0.f); v3 = fmaxf(v3, 0.f);
            }
            store2(C + (size_t)r0 * N + col, v0, v1);
            store2(C + (size_t)r1 * N + col, v2, v3);
        }
    }
}

// ================== fp32-input GEMM (vproj only; converts in-register) ==========
// C = A(MxK,f32) * B(KxN,f32) + bias -> bf16. Register-prefetch pipeline.
// Identical roundings to conv-then-bf16GEMM (same __floats2bfloat162_rn).
__global__ __launch_bounds__(256, 2) void hgemm_f32(
    const float* __restrict__ A, const float* __restrict__ B,
    const float* __restrict__ bias, __nv_bfloat16* __restrict__ C,
    int M, int N, int K)
{
    __shared__ __align__(16) __nv_bfloat16 As[2][128][40];
    __shared__ __align__(16) __nv_bfloat16 Bs[2][64][40];   // [n][k]
    const int tid = threadIdx.x;
    const int bm = blockIdx.x * 128, bn = blockIdx.y * 64;
    const int lane = tid & 31, w = tid >> 5;
    const int m0 = (w >> 1) * 32, n0 = (w & 1) * 32;

    float acc[2][4][4];
    #pragma unroll
    for (int i = 0; i < 2; i++)
        #pragma unroll
        for (int j = 0; j < 4; j++)
            #pragma unroll
            for (int l = 0; l < 4; l++) acc[i][j][l] = 0.0f;

    const int arow = tid >> 3, acol = (tid & 7) * 4;
    const int bk = tid >> 4, bn4 = (tid & 15) * 4;

    const float* Ap[4];
    #pragma unroll
    for (int p = 0; p < 4; p++) {
        int r = bm + arow + p * 32; r = r < M ? r : M - 1;
        Ap[p] = A + (size_t)r * K + acol;
    }
    const float* Bp0 = B + (size_t)bk * N + bn + bn4;
    const float* Bp1 = Bp0 + (size_t)16 * N;

    float4 arg[2][4];
    float4 brg[2][2];

#define G2R(s, k0) do {                                                        \
    _Pragma("unroll")                                                          \
    for (int p = 0; p < 4; p++) arg[s][p] = *(const float4*)(Ap[p] + (k0));    \
    brg[s][0] = *(const float4*)(Bp0 + (size_t)(k0) * N);                      \
    brg[s][1] = *(const float4*)(Bp1 + (size_t)(k0) * N);                      \
} while (0)

#define R2S(s, b) do {                                                         \
    _Pragma("unroll")                                                          \
    for (int p = 0; p < 4; p++) {                                              \
        int row = arow + p * 32;                                               \
        *(__nv_bfloat162*)&As[b][row][acol] =                                  \
            __floats2bfloat162_rn(arg[s][p].x, arg[s][p].y);                   \
        *(__nv_bfloat162*)&As[b][row][acol + 2] =                              \
            __floats2bfloat162_rn(arg[s][p].z, arg[s][p].w);                   \
    }                                                                          \
    _Pragma("unroll")                                                          \
    for (int p = 0; p < 2; p++) {                                              \
        int kk = bk + p * 16;                                                  \
        Bs[b][bn4 + 0][kk] = __float2bfloat16_rn(brg[s][p].x);                 \
        Bs[b][bn4 + 1][kk] = __float2bfloat16_rn(brg[s][p].y);                 \
        Bs[b][bn4 + 2][kk] = __float2bfloat16_rn(brg[s][p].z);                 \
        Bs[b][bn4 + 3][kk] = __float2bfloat16_rn(brg[s][p].w);                 \
    }                                                                          \
} while (0)

#define COMPUTE(b) do {                                                        \
    _Pragma("unroll")                                                          \
    for (int ks = 0; ks < 2; ks++) {                                           \
        uint32_t af[2][4], bfr[4][2];                                          \
        _Pragma("unroll")                                                      \
        for (int mt = 0; mt < 2; mt++)                                         \
            ldsm4(af[mt], &As[b][m0 + mt * 16 + (lane & 15)]                   \
                             [ks * 16 + ((lane >> 4) << 3)]);                  \
        _Pragma("unroll")                                                      \
        for (int nt2 = 0; nt2 < 2; nt2++) {                                    \
            uint32_t t[4];                                                     \
            ldsm4(t, &Bs[b][n0 + nt2 * 16 + (lane & 15)]                       \
                           [ks * 16 + ((lane >> 4) << 3)]);                    \
            bfr[nt2 * 2][0] = t[0];      bfr[nt2 * 2][1] = t[2];               \
            bfr[nt2 * 2 + 1][0] = t[1];  bfr[nt2 * 2 + 1][1] = t[3];           \
        }                                                                      \
        _Pragma("unroll")                                                      \
        for (int mt = 0; mt < 2; mt++)                                         \
            _Pragma("unroll")                                                  \
            for (int nt = 0; nt < 4; nt++)                                     \
                mma_bf16(acc[mt][nt], af[mt], bfr[nt]);                        \
    }                                                                          \
} while (0)

    const int KT = K >> 5;
    G2R(0, 0);
    R2S(0, 0);
    G2R(1, 32);
    __syncthreads();

    for (int kt = 0; kt < KT; kt += 2) {
        if (kt + 2 < KT) G2R(0, (kt + 2) * 32);
        COMPUTE(0);
        if (kt + 1 < KT) { R2S(1, 1); __syncthreads(); }
        if (kt + 3 < KT) G2R(1, (kt + 3) * 32);
        if (kt + 1 < KT) {
            COMPUTE(1);
            if (kt + 2 < KT) { R2S(0, 0); __syncthreads(); }
        }
    }
#undef G2R
#undef R2S
#undef COMPUTE

    const int row0 = bm + m0 + (lane >> 2);
    #pragma unroll
    for (int mt = 0; mt < 2; mt++) {
        int r0 = row0 + mt * 16, r1 = r0 + 8;
        #pragma unroll
        for (int nt = 0; nt < 4; nt++) {
            int col = bn + n0 + nt * 8 + ((lane & 3) << 1);
            float b0 = __ldg(bias + col), b1 = __ldg(bias + col + 1);
            float v0 = acc[mt][nt][0] + b0, v1 = acc[mt][nt][1] + b1;
            float v2 = acc[mt][nt][2] + b0, v3 = acc[mt][nt][3] + b1;
            if (r0 < M) store2(C + (size_t)r0 * N + col, v0, v1);
            if (r1 < M) store2(C + (size_t)r1 * N + col, v2, v3);
        }
    }
}

// ---------------- deformable sampling + cross-camera aggregation ----------------
// (exact R8 sampler — best measured)
__global__ __launch_bounds__(256) void sample_kernel(
    const float* __restrict__ ref)   // (6, 6400, 4, 2)
{
    __shared__ float4 sw[768];
    __shared__ int4 sidx[768];
    __shared__ float saw[128];
    __shared__ float4 sred[256][2];
    const int n = blockIdx.x;
    const int tid = threadIdx.x;
    const unsigned int vism = g_vis[n];

    // Phase 0: softmax over each 16-point group (8 heads)
    if (tid < 128) {
        float lv = g_fused[(size_t)n * NFUS + 256 + tid];
        float mx = lv;
        #pragma unroll
        for (int o = 8; o > 0; o >>= 1)
            mx = fmaxf(mx, __shfl_xor_sync(0xffffffffu, mx, o));
        float e = expf(lv - mx);
        float s = e;
        #pragma unroll
        for (int o = 8; o > 0; o >>= 1)
            s += __shfl_xor_sync(0xffffffffu, s, o);
        saw[tid] = e / s;
    }
    __syncthreads();

    // Phase 1: weights + corner row indices
    #pragma unroll
    for (int t = 0; t < 3; t++) {
        int cid = tid + t * 256;
        int k = cid >> 7;
        int r = cid & 127;          // h*16 + lvl*4 + p
        int h = r >> 4;
        int lvl = (r >> 2) & 3;
        int p = r & 3;
        float4 wv = make_float4(0.f, 0.f, 0.f, 0.f);
        int4 iv = make_int4(0, 0, 0, 0);
        if ((vism >> k) & 1) {
            int Wi = c_W[lvl], Hi = c_H[lvl];
            float Wf = (float)Wi, Hf = (float)Hi;
            const float* rp = ref + (((size_t)k * NQ + n) * 4 + lvl) * 2;
            float rx = rp[0], ry = rp[1];
            int oi = ((h * 4 + lvl) * 4 + p) * 2;
            float ox = g_fused[(size_t)n * NFUS + oi];
            float oy = g_fused[(size_t)n * NFUS + oi + 1];
            float x = (rx + ox / Wf) * Wf - 0.5f;
            float y = (ry + oy / Hf) * Hf - 0.5f;
            float x0f = floorf(x), y0f = floorf(y);
            float lx = x - x0f, ly = y - y0f;
            int x0 = (int)x0f, y0 = (int)y0f;
            float a = saw[r];
            bool vx0 = (x0 >= 0) && (x0 < Wi);
            bool vx1 = (x0 + 1 >= 0) && (x0 + 1 < Wi);
            bool vy0 = (y0 >= 0) && (y0 < Hi);
            bool vy1 = (y0 + 1 >= 0) && (y0 + 1 < Hi);
            float omx = 1.0f - lx, omy = 1.0f - ly;
            wv.x = (vx0 && vy0) ? a * omx * omy : 0.0f;
            wv.y = (vx1 && vy0) ? a * lx * omy : 0.0f;
            wv.z = (vx0 && vy1) ? a * omx * ly : 0.0f;
            wv.w = (vx1 && vy1) ? a * lx * ly : 0.0f;
            int xc0 = min(max(x0, 0), Wi - 1);
            int xc1 = min(max(x0 + 1, 0), Wi - 1);
            int yc0 = min(max(y0, 0), Hi - 1);
            int yc1 = min(max(y0 + 1, 0), Hi - 1);
            int rb = k * LTOT + c_S[lvl];
            int r0 = rb + yc0 * Wi, r1 = rb + yc1 * Wi;
            iv = make_int4(r0 + xc0, r0 + xc1, r1 + xc0, r1 + xc1);
        }
        sw[cid] = wv;
        sidx[cid] = iv;
    }
    __syncthreads();

    // Phase 2: gather + packed FMA
    const int cg = tid & 31;              // 8-channel group
    const int hh = cg >> 2;               // head
    const int pgrp = tid >> 5;            // handles points {2*pgrp, 2*pgrp+1}
    const __nv_bfloat16* vb = g_vproj + cg * 8;
    u64 a0 = 0, a1 = 0, a2 = 0, a3 = 0;

    #pragma unroll 1
    for (int k = 0; k < CAMS; k++) {
        if (!((vism >> k) & 1)) continue;
        const int base = k * 128 + hh * 16 + pgrp * 2;
        #pragma unroll
        for (int j = 0; j < 2; j++) {
            float4 w = sw[base + j];
            int4 iv = sidx[base + j];
            u64 w0 = pkf2(w.x, w.x), w1 = pkf2(w.y, w.y);
            u64 w2 = pkf2(w.z, w.z), w3 = pkf2(w.w, w.w);
            uint4 q0 = *(const uint4*)(vb + ((size_t)iv.x << 8));
            uint4 q1 = *(const uint4*)(vb + ((size_t)iv.y << 8));
            uint4 q2 = *(const uint4*)(vb + ((size_t)iv.z << 8));
            uint4 q3 = *(const uint4*)(vb + ((size_t)iv.w << 8));
            ffma2(a0, w0, bf2f2(q0.x)); ffma2(a1, w0, bf2f2(q0.y));
            ffma2(a2, w0, bf2f2(q0.z)); ffma2(a3, w0, bf2f2(q0.w));
            ffma2(a0, w1, bf2f2(q1.x)); ffma2(a1, w1, bf2f2(q1.y));
            ffma2(a2, w1, bf2f2(q1.z)); ffma2(a3, w1, bf2f2(q1.w));
            ffma2(a0, w2, bf2f2(q2.x)); ffma2(a1, w2, bf2f2(q2.y));
            ffma2(a2, w2, bf2f2(q2.z)); ffma2(a3, w2, bf2f2(q2.w));
            ffma2(a0, w3, bf2f2(q3.x)); ffma2(a1, w3, bf2f2(q3.y));
            ffma2(a2, w3, bf2f2(q3.z)); ffma2(a3, w3, bf2f2(q3.w));
        }
    }

    float2 f0 = upk(a0), f1 = upk(a1), f2 = upk(a2), f3 = upk(a3);
    sred[tid][0] = make_float4(f0.x, f0.y, f1.x, f1.y);
    sred[tid][1] = make_float4(f2.x, f2.y, f3.x, f3.y);
    __syncthreads();
    if (tid < 128) {
        float4 x0 = sred[tid + 128][0], x1 = sred[tid + 128][1];
        float4 y0 = sred[tid][0], y1 = sred[tid][1];
        y0.x += x0.x; y0.y += x0.y; y0.z += x0.z; y0.w += x0.w;
        y1.x += x1.x; y1.y += x1.y; y1.z += x1.z; y1.w += x1.w;
        sred[tid][0] = y0; sred[tid][1] = y1;
    }
    __syncthreads();
    if (tid < 64) {
        float4 x0 = sred[tid + 64][0], x1 = sred[tid + 64][1];
        float4 y0 = sred[tid][0], y1 = sred[tid][1];
        y0.x += x0.x; y0.y += x0.y; y0.z += x0.z; y0.w += x0.w;
        y1.x += x1.x; y1.y += x1.y; y1.z += x1.z; y1.w += x1.w;
        sred[tid][0] = y0; sred[tid][1] = y1;
    }
    __syncthreads();
    if (tid < 32) {
        float4 x0 = sred[tid + 32][0], x1 = sred[tid + 32][1];
        float4 y0 = sred[tid][0], y1 = sred[tid][1];
        y0.x += x0.x; y0.y += x0.y; y0.z += x0.z; y0.w += x0.w;
        y1.x += x1.x; y1.y += x1.y; y1.z += x1.z; y1.w += x1.w;
        __nv_bfloat162 p0 = __floats2bfloat162_rn(y0.x, y0.y);
        __nv_bfloat162 p1 = __floats2bfloat162_rn(y0.z, y0.w);
        __nv_bfloat162 p2 = __floats2bfloat162_rn(y1.x, y1.y);
        __nv_bfloat162 p3 = __floats2bfloat162_rn(y1.z, y1.w);
        uint4 pk;
        pk.x = *(uint32_t*)&p0; pk.y = *(uint32_t*)&p1;
        pk.z = *(uint32_t*)&p2; pk.w = *(uint32_t*)&p3;
        *(uint4*)(g_aggh + (size_t)n * CH + tid * 8) = pk;
    }
}

// ---------------- block reduction helper ----------------
__device__ __forceinline__ float blocksum256(float v, float* sh) {
    #pragma unroll
    for (int o = 16; o > 0; o >>= 1) v += __shfl_xor_sync(0xffffffffu, v, o);
    if ((threadIdx.x & 31) == 0) sh[threadIdx.x >> 5] = v;
    __syncthreads();
    float s = 0.f;
    #pragma unroll
    for (int i = 0; i < 8; i++) s += sh[i];
    __syncthreads();
    return s;
}

// ---------------- slots assembly + residual + LN1 ----------------
__global__ __launch_bounds__(256) void ln1_kernel(
    const float* __restrict__ query, const float* __restrict__ b_out,
    const float* __restrict__ gamma, const float* __restrict__ beta)
{
    __shared__ float sh[8];
    const int n = blockIdx.x, c = threadIdx.x;
    float m = g_cnt[n];
    float q = query[(size_t)n * CH + c];
    float s = m * (q + b_out[c]) + g_proj[(size_t)n * CH + c];
    float t = s / fmaxf(m, 1.0f) + q;
    float mu = blocksum256(t, sh) * (1.0f / CH);
    float d = t - mu;
    float var = blocksum256(d * d, sh) * (1.0f / CH);
    float xv = d * rsqrtf(var + 1e-5f) * gamma[c] + beta[c];
    g_x[(size_t)n * CH + c] = xv;
    g_x_h[(size_t)n * CH + c] = __float2bfloat16_rn(xv);
}

// ---------------- FFN residual + LN2 -> output ----------------
__global__ __launch_bounds__(256) void ln2_kernel(
    const float* __restrict__ gamma, const float* __restrict__ beta,
    float* __restrict__ out)
{
    __shared__ float sh[8];
    const int n = blockIdx.x, c = threadIdx.x;
    float t = g_x[(size_t)n * CH + c] + g_ffn2[(size_t)n * CH + c];
    float mu = blocksum256(t, sh) * (1.0f / CH);
    float d = t - mu;
    float var = blocksum256(d * d, sh) * (1.0f / CH);
    out[(size_t)n * CH + c] = d * rsqrtf(var + 1e-5f) * gamma[c] + beta[c];
}

// ---------------- host launcher ----------------
extern "C" void kernel_launch(void* const* d_in, const int* in_sizes, int n_in,
                              void* d_out, int out_size) {
    const float* query   = (const float*)d_in[0];
    const float* value   = (const float*)d_in[2];
    const float* refpts  = (const float*)d_in[3];
    const int*   bev     = (const int*)d_in[6];
    const float* W_value = (const float*)d_in[7];
    const float* b_value = (const float*)d_in[8];
    const float* W_off   = (const float*)d_in[9];
    const float* b_off   = (const float*)d_in[10];
    const float* W_attn  = (const float*)d_in[11];
    const float* b_attn  = (const float*)d_in[12];
    const float* W_out   = (const float*)d_in[13];
    const float* b_out   = (const float*)d_in[14];
    const float* ln1_g   = (const float*)d_in[15];
    const float* ln1_b   = (const float*)d_in[16];
    const float* W1      = (const float*)d_in[17];
    const float* b1      = (const float*)d_in[18];
    const float* W2      = (const float*)d_in[19];
    const float* b2      = (const float*)d_in[20];
    const float* ln2_g   = (const float*)d_in[21];
    const float* ln2_b   = (const float*)d_in[22];
    float* out = (float*)d_out;

    void *p_vproj, *p_qh, *p_Wfh, *p_bf, *p_Wouth, *p_W1h, *p_W2h;
    void *p_fused, *p_aggh, *p_proj, *p_xh, *p_ffn1h, *p_ffn2;
    cudaGetSymbolAddress(&p_vproj,  g_vproj);
    cudaGetSymbolAddress(&p_qh,     g_q_h);
    cudaGetSymbolAddress(&p_Wfh,    g_Wf_h);
    cudaGetSymbolAddress(&p_bf,     g_bf);
    cudaGetSymbolAddress(&p_Wouth,  g_Wout_h);
    cudaGetSymbolAddress(&p_W1h,    g_W1_h);
    cudaGetSymbolAddress(&p_W2h,    g_W2_h);
    cudaGetSymbolAddress(&p_fused,  g_fused);
    cudaGetSymbolAddress(&p_aggh,   g_aggh);
    cudaGetSymbolAddress(&p_proj,   g_proj);
    cudaGetSymbolAddress(&p_xh,     g_x_h);
    cudaGetSymbolAddress(&p_ffn1h,  g_ffn1h);
    cudaGetSymbolAddress(&p_ffn2,   g_ffn2);

    static cudaStream_t s2 = nullptr;
    static cudaEvent_t ev_fork = nullptr, ev_join = nullptr;
    if (s2 == nullptr) {
        cudaStreamCreateWithFlags(&s2, cudaStreamNonBlocking);
        cudaEventCreateWithFlags(&ev_fork, cudaEventDisableTiming);
        cudaEventCreateWithFlags(&ev_join, cudaEventDisableTiming);
    }

    // ---- fork: vproj GEMM (fp32 in, bf16 out, converts in-register) on s2 ----
    cudaEventRecord(ev_fork, 0);
    cudaStreamWaitEvent(s2, ev_fork, 0);
    hgemm_f32<<<dim3((MVAL + 127) / 128, CH / 64), 256, 0, s2>>>(
        value, W_value, b_value, (__nv_bfloat16*)p_vproj, MVAL, CH, CH);
    cudaEventRecord(ev_join, s2);

    // ---- main stream: prep + fused off/attn GEMM ----
    prep_kernel<<<2585, 256>>>(bev, query, W_off, W_attn, b_off, b_attn,
                               W_out, W1, W2);
    hgemm_bf16<1, float><<<dim3(NQ / 128, NFUS / 64), 256>>>(
        (const __nv_bfloat16*)p_qh, (const __nv_bfloat16*)p_Wfh,
        (const float*)p_bf, (float*)p_fused, NQ, NFUS, CH);

    // ---- join, then sampling ----
    cudaStreamWaitEvent(0, ev_join, 0);
    sample_kernel<<<NQ, 256>>>(refpts);

    // output projection: agg(bf16) @ W_out (bias folded into ln1)
    hgemm_bf16<0, float><<<dim3(NQ / 128, CH / 64), 256>>>(
        (const __nv_bfloat16*)p_aggh, (const __nv_bfloat16*)p_Wouth,
        nullptr, (float*)p_proj, NQ, CH, CH);

    // slots + residual + LN1
    ln1_kernel<<<NQ, 256>>>(query, b_out, ln1_g, ln1_b);

    // FFN up: relu(x @ W1 + b1) -> bf16
    hgemm_bf16<2, __nv_bfloat16><<<dim3(NQ / 128, DFFN / 64), 256>>>(
        (const __nv_bfloat16*)p_xh, (const __nv_bfloat16*)p_W1h,
        b1, (__nv_bfloat16*)p_ffn1h, NQ, DFFN, CH);

    // FFN down: ffn1(bf16) @ W2 + b2
    hgemm_bf16<1, float><<<dim3(NQ / 128, CH / 64), 256>>>(
        (const __nv_bfloat16*)p_ffn1h, (const __nv_bfloat16*)p_W2h,
        b2, (float*)p_ffn2, NQ, CH, DFFN);

    // residual + LN2 -> out
    ln2_kernel<<<NQ, 256>>>(ln2_g, ln2_b, out);

    (void)in_sizes; (void)n_in; (void)out_size;
}

// round 14
// speedup vs baseline: 1.1039x; 1.0638x over previous
#include <cuda_runtime.h>
#include <cuda_bf16.h>
#include <stdint.h>

// Problem constants (fixed by setup_inputs)
#define NQ   6400
#define CAMS 6
#define LTOT 7979
#define CH   256
#define DFFN 1024
#define NFUS 384   // fused off(256) + attn-logits(128)
#define MVAL (CAMS * LTOT)   // 47874
#define MPAD 48000           // 375 * 128

typedef unsigned long long u64;

// ---------------- scratch (static device globals; no allocation) ----------------
__device__ __nv_bfloat16 g_val_h[MPAD * CH];        // value in bf16 (padded rows stay 0)
__device__ __nv_bfloat16 g_Wval_h[CH * CH];         // W_value bf16
__device__ __nv_bfloat16 g_vproj[MPAD * CH];        // value @ W_value + b (bf16)
__device__ __nv_bfloat16 g_q_h[NQ * CH];            // query in bf16
__device__ __nv_bfloat16 g_Wf_h[CH * NFUS];         // fused [W_off | W_attn] bf16
__device__ float g_bf[NFUS];                        // fused bias (fp32)
__device__ __nv_bfloat16 g_Wout_h[CH * CH];         // W_out bf16
__device__ __nv_bfloat16 g_W1_h[CH * DFFN];         // W1 bf16
__device__ __nv_bfloat16 g_W2_h[DFFN * CH];         // W2 bf16
__device__ float g_fused[NQ * NFUS];                // fused offsets + attn logits
__device__ __nv_bfloat16 g_aggh[NQ * CH];           // aggregated samples (bf16)
__device__ float g_proj[NQ * CH];                   // agg @ W_out
__device__ float g_x[NQ * CH];                      // after LN1 (fp32)
__device__ __nv_bfloat16 g_x_h[NQ * CH];            // after LN1 (bf16)
__device__ __nv_bfloat16 g_ffn1h[NQ * DFFN];        // relu(x@W1+b1) (bf16)
__device__ float g_ffn2[NQ * CH];                   // ffn1@W2+b2
__device__ unsigned int g_vis[NQ];                  // camera visibility bitmask
__device__ float g_cnt[NQ];                         // number of visible cameras

__constant__ int c_W[4] = {100, 50, 25, 13};
__constant__ int c_H[4] = {60, 30, 15, 8};
__constant__ int c_S[4] = {0, 6000, 7500, 7875};

// ---------------- f32x2 packed-math helpers ----------------
__device__ __forceinline__ u64 pkf2(float lo, float hi) {
    u64 r; asm("mov.b64 %0, {%1, %2};" : "=l"(r) : "f"(lo), "f"(hi)); return r;
}
__device__ __forceinline__ u64 bf2f2(uint32_t v) {
    uint32_t lo = v << 16, hi = v & 0xFFFF0000u;
    u64 r; asm("mov.b64 %0, {%1, %2};" : "=l"(r) : "r"(lo), "r"(hi)); return r;
}
__device__ __forceinline__ void ffma2(u64& d, u64 a, u64 b) {
    asm("fma.rn.f32x2 %0, %1, %2, %0;" : "+l"(d) : "l"(a), "l"(b));
}
__device__ __forceinline__ float2 upk(u64 v) {
    float2 f; asm("mov.b64 {%0, %1}, %2;" : "=f"(f.x), "=f"(f.y) : "l"(v)); return f;
}

// ---------------- fused prep: mask + query/weight fp32->bf16 ----------------
__global__ __launch_bounds__(256) void prep_kernel(
    const int* __restrict__ bev, const float* __restrict__ query,
    const float* __restrict__ Woff, const float* __restrict__ Wattn,
    const float* __restrict__ boff, const float* __restrict__ battn,
    const float* __restrict__ Wout, const float* __restrict__ W1,
    const float* __restrict__ W2)
{
    const int b = blockIdx.x, tid = threadIdx.x;
    if (b < 25) {
        int n = b * 256 + tid;
        unsigned int vm = 0; int cnt = 0;
        #pragma unroll
        for (int k = 0; k < CAMS; k++) {
            const int* bp = bev + ((size_t)k * NQ + n) * 4;
            if (bp[0] + bp[1] + bp[2] + bp[3] > 0) { vm |= (1u << k); cnt++; }
        }
        g_vis[n] = vm;
        g_cnt[n] = (float)cnt;
    } else if (b < 1625) {
        int i = (b - 25) * 256 + tid;           // float4 index, < 409600
        float4 v = ((const float4*)query)[i];
        ((__nv_bfloat162*)g_q_h)[i * 2]     = __floats2bfloat162_rn(v.x, v.y);
        ((__nv_bfloat162*)g_q_h)[i * 2 + 1] = __floats2bfloat162_rn(v.z, v.w);
    } else if (b < 2009) {
        int i = (b - 1625) * 256 + tid;         // < 98304
        int k = i / NFUS, n = i % NFUS;
        float v = (n < 256) ? Woff[k * 256 + n] : Wattn[k * 128 + (n - 256)];
        g_Wf_h[i] = __float2bfloat16_rn(v);
        if (i < NFUS) g_bf[i] = (i < 256) ? boff[i] : battn[i - 256];
    } else if (b < 2073) {
        int i = (b - 2009) * 256 + tid;         // < 16384
        float4 v = ((const float4*)Wout)[i];
        ((__nv_bfloat162*)g_Wout_h)[i * 2]     = __floats2bfloat162_rn(v.x, v.y);
        ((__nv_bfloat162*)g_Wout_h)[i * 2 + 1] = __floats2bfloat162_rn(v.z, v.w);
    } else if (b < 2329) {
        int i = (b - 2073) * 256 + tid;         // < 65536
        float4 v = ((const float4*)W1)[i];
        ((__nv_bfloat162*)g_W1_h)[i * 2]     = __floats2bfloat162_rn(v.x, v.y);
        ((__nv_bfloat162*)g_W1_h)[i * 2 + 1] = __floats2bfloat162_rn(v.z, v.w);
    } else {
        int i = (b - 2329) * 256 + tid;         // < 65536
        float4 v = ((const float4*)W2)[i];
        ((__nv_bfloat162*)g_W2_h)[i * 2]     = __floats2bfloat162_rn(v.x, v.y);
        ((__nv_bfloat162*)g_W2_h)[i * 2 + 1] = __floats2bfloat162_rn(v.z, v.w);
    }
}

// ---------------- value + W_value fp32 -> bf16 (stream 2) ----------------
__global__ __launch_bounds__(256) void conv_val_kernel(
    const float* __restrict__ val, const float* __restrict__ Wv)
{
    const int NV = MVAL * CH / 4;   // 3,063,936
    int i = blockIdx.x * 256 + threadIdx.x;
    if (i < NV) {
        float4 v = ((const float4*)val)[i];
        ((__nv_bfloat162*)g_val_h)[i * 2]     = __floats2bfloat162_rn(v.x, v.y);
        ((__nv_bfloat162*)g_val_h)[i * 2 + 1] = __floats2bfloat162_rn(v.z, v.w);
    } else {
        int j = i - NV;
        if (j < CH * CH / 4) {
            float4 v = ((const float4*)Wv)[j];
            ((__nv_bfloat162*)g_Wval_h)[j * 2]     = __floats2bfloat162_rn(v.x, v.y);
            ((__nv_bfloat162*)g_Wval_h)[j * 2 + 1] = __floats2bfloat162_rn(v.z, v.w);
        }
    }
}

// ---------------- tensor-core GEMM building blocks ----------------
__device__ __forceinline__ void ldsm4(uint32_t* r, const void* p) {
    uint32_t a = (uint32_t)__cvta_generic_to_shared(p);
    asm volatile("ldmatrix.sync.aligned.m8n8.x4.shared.b16 {%0,%1,%2,%3}, [%4];"
                 : "=r"(r[0]), "=r"(r[1]), "=r"(r[2]), "=r"(r[3]) : "r"(a));
}
__device__ __forceinline__ void ldsm4t(uint32_t* r, const void* p) {
    uint32_t a = (uint32_t)__cvta_generic_to_shared(p);
    asm volatile("ldmatrix.sync.aligned.m8n8.x4.trans.shared.b16 {%0,%1,%2,%3}, [%4];"
                 : "=r"(r[0]), "=r"(r[1]), "=r"(r[2]), "=r"(r[3]) : "r"(a));
}
__device__ __forceinline__ void mma_bf16(float* d, const uint32_t* a, const uint32_t* b) {
    asm volatile("mma.sync.aligned.m16n8k16.row.col.f32.bf16.bf16.f32 "
                 "{%0,%1,%2,%3}, {%4,%5,%6,%7}, {%8,%9}, {%0,%1,%2,%3};"
                 : "+f"(d[0]), "+f"(d[1]), "+f"(d[2]), "+f"(d[3])
                 : "r"(a[0]), "r"(a[1]), "r"(a[2]), "r"(a[3]), "r"(b[0]), "r"(b[1]));
}
__device__ __forceinline__ void cpa16(void* dst, const void* src) {
    uint32_t d = (uint32_t)__cvta_generic_to_shared(dst);
    asm volatile("cp.async.cg.shared.global [%0], [%1], 16;" :: "r"(d), "l"(src));
}
__device__ __forceinline__ void store2(float* C, float x, float y) {
    *(float2*)C = make_float2(x, y);
}
__device__ __forceinline__ void store2(__nv_bfloat16* C, float x, float y) {
    *(__nv_bfloat162*)C = __floats2bfloat162_rn(x, y);
}

// ================== bf16 cp.async GEMM ==================
// C(MxN) = A(MxK,bf16 rm) * B(KxN,bf16 rm) (+bias)(+relu). 128x64 tile, BK=32,
// 4-stage cp.async, 256 thr (8 warps x 32x32). M%128==0, N%64==0, K%32==0.
#define STAGES 4
template<int EPI, typename OutT>
__global__ __launch_bounds__(256, 2) void hgemm_bf16(
    const __nv_bfloat16* __restrict__ A, const __nv_bfloat16* __restrict__ B,
    const float* __restrict__ bias, OutT* __restrict__ C,
    int M, int N, int K)
{
    __shared__ __align__(16) __nv_bfloat16 As[STAGES][128][40];
    __shared__ __align__(16) __nv_bfloat16 Bs[STAGES][32][72];   // [k][n]
    const int tid = threadIdx.x;
    const int bm = blockIdx.x * 128, bn = blockIdx.y * 64;
    const int lane = tid & 31, w = tid >> 5;
    const int m0 = (w >> 1) * 32, n0 = (w & 1) * 32;

    float acc[2][4][4];
    #pragma unroll
    for (int i = 0; i < 2; i++)
        #pragma unroll
        for (int j = 0; j < 4; j++)
            #pragma unroll
            for (int l = 0; l < 4; l++) acc[i][j][l] = 0.0f;

    const int arow = tid >> 1, acol = (tid & 1) * 16;
    const int brow = tid >> 3, bcol = (tid & 7) * 8;

    const __nv_bfloat16* Asrc = A + (size_t)(bm + arow) * K + acol;
    const __nv_bfloat16* Bsrc = B + bn + bcol;

    const int KT = K >> 5;

#define ISSUE(s, kt) do {                                                      \
    cpa16(&As[s][arow][acol],     Asrc + (kt) * 32);                           \
    cpa16(&As[s][arow][acol + 8], Asrc + (kt) * 32 + 8);                       \
    cpa16(&Bs[s][brow][bcol],     Bsrc + (size_t)((kt) * 32 + brow) * N);      \
} while (0)

#define COMPUTE_T(b) do {                                                      \
    _Pragma("unroll")                                                          \
    for (int ks = 0; ks < 2; ks++) {                                           \
        uint32_t af[2][4], bfr[4][2];                                          \
        _Pragma("unroll")                                                      \
        for (int mt = 0; mt < 2; mt++)                                         \
            ldsm4(af[mt], &As[b][m0 + mt * 16 + (lane & 15)]                   \
                             [ks * 16 + ((lane >> 4) << 3)]);                  \
        _Pragma("unroll")                                                      \
        for (int nt2 = 0; nt2 < 2; nt2++) {                                    \
            uint32_t t[4];                                                     \
            ldsm4t(t, &Bs[b][ks * 16 + (lane & 7) + 8 * ((lane >> 3) & 1)]     \
                            [n0 + nt2 * 16 + 8 * (lane >> 4)]);                \
            bfr[nt2 * 2][0] = t[0];      bfr[nt2 * 2][1] = t[1];               \
            bfr[nt2 * 2 + 1][0] = t[2];  bfr[nt2 * 2 + 1][1] = t[3];           \
        }                                                                      \
        _Pragma("unroll")                                                      \
        for (int mt = 0; mt < 2; mt++)                                         \
            _Pragma("unroll")                                                  \
            for (int nt = 0; nt < 4; nt++)                                     \
                mma_bf16(acc[mt][nt], af[mt], bfr[nt]);                        \
    }                                                                          \
} while (0)

    #pragma unroll
    for (int s = 0; s < STAGES - 1; s++) {
        if (s < KT) ISSUE(s, s);
        asm volatile("cp.async.commit_group;");
    }

    for (int kt = 0; kt < KT; kt++) {
        asm volatile("cp.async.wait_group %0;" :: "n"(STAGES - 2));
        __syncthreads();
        int kn = kt + STAGES - 1;
        if (kn < KT) ISSUE(kn & (STAGES - 1), kn);
        asm volatile("cp.async.commit_group;");
        COMPUTE_T(kt & (STAGES - 1));
    }
#undef ISSUE
#undef COMPUTE_T

    const int row0 = bm + m0 + (lane >> 2);
    #pragma unroll
    for (int mt = 0; mt < 2; mt++) {
        int r0 = row0 + mt * 16, r1 = r0 + 8;
        #pragma unroll
        for (int nt = 0; nt < 4; nt++) {
            int col = bn + n0 + nt * 8 + ((lane & 3) << 1);
            float b0 = 0.f, b1 = 0.f;
            if (EPI >= 1) { b0 = __ldg(bias + col); b1 = __ldg(bias + col + 1); }
            float v0 = acc[mt][nt][0] + b0, v1 = acc[mt][nt][1] + b1;
            float v2 = acc[mt][nt][2] + b0, v3 = acc[mt][nt][3] + b1;
            if (EPI == 2) {
                v0 = fmaxf(v0, 0.f); v1 = fmaxf(v1, 0.f);
                v2 = fmaxf(v2, 0.f); v3 = fmaxf(v3, 0.f);
            }
            store2(C + (size_t)r0 * N + col, v0, v1);
            store2(C + (size_t)r1 * N + col, v2, v3);
        }
    }
}

// ---------------- deformable sampling + cross-camera aggregation ----------------
// Exact R8 logic; smem reduced 33 -> 24.5 KB by aliasing sred onto sw (dead
// after phase 2; one extra barrier makes the aliasing safe) -> 8 CTAs/SM.
__global__ __launch_bounds__(256) void sample_kernel(
    const float* __restrict__ ref)   // (6, 6400, 4, 2)
{
    __shared__ __align__(16) char smem_raw[25088];
    float4* sw = (float4*)smem_raw;                       // [768], 12288 B
    int4* sidx = (int4*)(smem_raw + 12288);               // [768], 12288 B
    float* saw = (float*)(smem_raw + 24576);              // [128], 512 B
    float4 (*sred)[2] = (float4(*)[2])smem_raw;           // [256][2] aliases sw
    const int n = blockIdx.x;
    const int tid = threadIdx.x;
    const unsigned int vism = g_vis[n];

    // Phase 0: softmax over each 16-point group (8 heads)
    if (tid < 128) {
        float lv = g_fused[(size_t)n * NFUS + 256 + tid];
        float mx = lv;
        #pragma unroll
        for (int o = 8; o > 0; o >>= 1)
            mx = fmaxf(mx, __shfl_xor_sync(0xffffffffu, mx, o));
        float e = expf(lv - mx);
        float s = e;
        #pragma unroll
        for (int o = 8; o > 0; o >>= 1)
            s += __shfl_xor_sync(0xffffffffu, s, o);
        saw[tid] = e / s;
    }
    __syncthreads();

    // Phase 1: weights + corner row indices
    #pragma unroll
    for (int t = 0; t < 3; t++) {
        int cid = tid + t * 256;
        int k = cid >> 7;
        int r = cid & 127;          // h*16 + lvl*4 + p
        int h = r >> 4;
        int lvl = (r >> 2) & 3;
        int p = r & 3;
        float4 wv = make_float4(0.f, 0.f, 0.f, 0.f);
        int4 iv = make_int4(0, 0, 0, 0);
        if ((vism >> k) & 1) {
            int Wi = c_W[lvl], Hi = c_H[lvl];
            float Wf = (float)Wi, Hf = (float)Hi;
            const float* rp = ref + (((size_t)k * NQ + n) * 4 + lvl) * 2;
            float rx = rp[0], ry = rp[1];
            int oi = ((h * 4 + lvl) * 4 + p) * 2;
            float ox = g_fused[(size_t)n * NFUS + oi];
            float oy = g_fused[(size_t)n * NFUS + oi + 1];
            float x = (rx + ox / Wf) * Wf - 0.5f;
            float y = (ry + oy / Hf) * Hf - 0.5f;
            float x0f = floorf(x), y0f = floorf(y);
            float lx = x - x0f, ly = y - y0f;
            int x0 = (int)x0f, y0 = (int)y0f;
            float a = saw[r];
            bool vx0 = (x0 >= 0) && (x0 < Wi);
            bool vx1 = (x0 + 1 >= 0) && (x0 + 1 < Wi);
            bool vy0 = (y0 >= 0) && (y0 < Hi);
            bool vy1 = (y0 + 1 >= 0) && (y0 + 1 < Hi);
            float omx = 1.0f - lx, omy = 1.0f - ly;
            wv.x = (vx0 && vy0) ? a * omx * omy : 0.0f;
            wv.y = (vx1 && vy0) ? a * lx * omy : 0.0f;
            wv.z = (vx0 && vy1) ? a * omx * ly : 0.0f;
            wv.w = (vx1 && vy1) ? a * lx * ly : 0.0f;
            int xc0 = min(max(x0, 0), Wi - 1);
            int xc1 = min(max(x0 + 1, 0), Wi - 1);
            int yc0 = min(max(y0, 0), Hi - 1);
            int yc1 = min(max(y0 + 1, 0), Hi - 1);
            int rb = k * LTOT + c_S[lvl];
            int r0 = rb + yc0 * Wi, r1 = rb + yc1 * Wi;
            iv = make_int4(r0 + xc0, r0 + xc1, r1 + xc0, r1 + xc1);
        }
        sw[cid] = wv;
        sidx[cid] = iv;
    }
    __syncthreads();

    // Phase 2: gather + packed FMA
    const int cg = tid & 31;              // 8-channel group
    const int hh = cg >> 2;               // head
    const int pgrp = tid >> 5;            // handles points {2*pgrp, 2*pgrp+1}
    const __nv_bfloat16* vb = g_vproj + cg * 8;
    u64 a0 = 0, a1 = 0, a2 = 0, a3 = 0;

    #pragma unroll 1
    for (int k = 0; k < CAMS; k++) {
        if (!((vism >> k) & 1)) continue;
        const int base = k * 128 + hh * 16 + pgrp * 2;
        #pragma unroll
        for (int j = 0; j < 2; j++) {
            float4 w = sw[base + j];
            int4 iv = sidx[base + j];
            u64 w0 = pkf2(w.x, w.x), w1 = pkf2(w.y, w.y);
            u64 w2 = pkf2(w.z, w.z), w3 = pkf2(w.w, w.w);
            uint4 q0 = *(const uint4*)(vb + ((size_t)iv.x << 8));
            uint4 q1 = *(const uint4*)(vb + ((size_t)iv.y << 8));
            uint4 q2 = *(const uint4*)(vb + ((size_t)iv.z << 8));
            uint4 q3 = *(const uint4*)(vb + ((size_t)iv.w << 8));
            ffma2(a0, w0, bf2f2(q0.x)); ffma2(a1, w0, bf2f2(q0.y));
            ffma2(a2, w0, bf2f2(q0.z)); ffma2(a3, w0, bf2f2(q0.w));
            ffma2(a0, w1, bf2f2(q1.x)); ffma2(a1, w1, bf2f2(q1.y));
            ffma2(a2, w1, bf2f2(q1.z)); ffma2(a3, w1, bf2f2(q1.w));
            ffma2(a0, w2, bf2f2(q2.x)); ffma2(a1, w2, bf2f2(q2.y));
            ffma2(a2, w2, bf2f2(q2.z)); ffma2(a3, w2, bf2f2(q2.w));
            ffma2(a0, w3, bf2f2(q3.x)); ffma2(a1, w3, bf2f2(q3.y));
            ffma2(a2, w3, bf2f2(q3.z)); ffma2(a3, w3, bf2f2(q3.w));
        }
    }

    // All reads of sw/sidx are done; safe to overwrite the aliased region.
    __syncthreads();
    float2 f0 = upk(a0), f1 = upk(a1), f2 = upk(a2), f3 = upk(a3);
    sred[tid][0] = make_float4(f0.x, f0.y, f1.x, f1.y);
    sred[tid][1] = make_float4(f2.x, f2.y, f3.x, f3.y);
    __syncthreads();
    if (tid < 128) {
        float4 x0 = sred[tid + 128][0], x1 = sred[tid + 128][1];
        float4 y0 = sred[tid][0], y1 = sred[tid][1];
        y0.x += x0.x; y0.y += x0.y; y0.z += x0.z; y0.w += x0.w;
        y1.x += x1.x; y1.y += x1.y; y1.z += x1.z; y1.w += x1.w;
        sred[tid][0] = y0; sred[tid][1] = y1;
    }
    __syncthreads();
    if (tid < 64) {
        float4 x0 = sred[tid + 64][0], x1 = sred[tid + 64][1];
        float4 y0 = sred[tid][0], y1 = sred[tid][1];
        y0.x += x0.x; y0.y += x0.y; y0.z += x0.z; y0.w += x0.w;
        y1.x += x1.x; y1.y += x1.y; y1.z += x1.z; y1.w += x1.w;
        sred[tid][0] = y0; sred[tid][1] = y1;
    }
    __syncthreads();
    if (tid < 32) {
        float4 x0 = sred[tid + 32][0], x1 = sred[tid + 32][1];
        float4 y0 = sred[tid][0], y1 = sred[tid][1];
        y0.x += x0.x; y0.y += x0.y; y0.z += x0.z; y0.w += x0.w;
        y1.x += x1.x; y1.y += x1.y; y1.z += x1.z; y1.w += x1.w;
        __nv_bfloat162 p0 = __floats2bfloat162_rn(y0.x, y0.y);
        __nv_bfloat162 p1 = __floats2bfloat162_rn(y0.z, y0.w);
        __nv_bfloat162 p2 = __floats2bfloat162_rn(y1.x, y1.y);
        __nv_bfloat162 p3 = __floats2bfloat162_rn(y1.z, y1.w);
        uint4 pk;
        pk.x = *(uint32_t*)&p0; pk.y = *(uint32_t*)&p1;
        pk.z = *(uint32_t*)&p2; pk.w = *(uint32_t*)&p3;
        *(uint4*)(g_aggh + (size_t)n * CH + tid * 8) = pk;
    }
}

// ---------------- block reduction helper ----------------
__device__ __forceinline__ float blocksum256(float v, float* sh) {
    #pragma unroll
    for (int o = 16; o > 0; o >>= 1) v += __shfl_xor_sync(0xffffffffu, v, o);
    if ((threadIdx.x & 31) == 0) sh[threadIdx.x >> 5] = v;
    __syncthreads();
    float s = 0.f;
    #pragma unroll
    for (int i = 0; i < 8; i++) s += sh[i];
    __syncthreads();
    return s;
}

// ---------------- slots assembly + residual + LN1 ----------------
__global__ __launch_bounds__(256) void ln1_kernel(
    const float* __restrict__ query, const float* __restrict__ b_out,
    const float* __restrict__ gamma, const float* __restrict__ beta)
{
    __shared__ float sh[8];
    const int n = blockIdx.x, c = threadIdx.x;
    float m = g_cnt[n];
    float q = query[(size_t)n * CH + c];
    float s = m * (q + b_out[c]) + g_proj[(size_t)n * CH + c];
    float t = s / fmaxf(m, 1.0f) + q;
    float mu = blocksum256(t, sh) * (1.0f / CH);
    float d = t - mu;
    float var = blocksum256(d * d, sh) * (1.0f / CH);
    float xv = d * rsqrtf(var + 1e-5f) * gamma[c] + beta[c];
    g_x[(size_t)n * CH + c] = xv;
    g_x_h[(size_t)n * CH + c] = __float2bfloat16_rn(xv);
}

// ---------------- FFN residual + LN2 -> output ----------------
__global__ __launch_bounds__(256) void ln2_kernel(
    const float* __restrict__ gamma, const float* __restrict__ beta,
    float* __restrict__ out)
{
    __shared__ float sh[8];
    const int n = blockIdx.x, c = threadIdx.x;
    float t = g_x[(size_t)n * CH + c] + g_ffn2[(size_t)n * CH + c];
    float mu = blocksum256(t, sh) * (1.0f / CH);
    float d = t - mu;
    float var = blocksum256(d * d, sh) * (1.0f / CH);
    out[(size_t)n * CH + c] = d * rsqrtf(var + 1e-5f) * gamma[c] + beta[c];
}

// ---------------- host launcher ----------------
extern "C" void kernel_launch(void* const* d_in, const int* in_sizes, int n_in,
                              void* d_out, int out_size) {
    const float* query   = (const float*)d_in[0];
    const float* value   = (const float*)d_in[2];
    const float* refpts  = (const float*)d_in[3];
    const int*   bev     = (const int*)d_in[6];
    const float* W_value = (const float*)d_in[7];
    const float* b_value = (const float*)d_in[8];
    const float* W_off   = (const float*)d_in[9];
    const float* b_off   = (const float*)d_in[10];
    const float* W_attn  = (const float*)d_in[11];
    const float* b_attn  = (const float*)d_in[12];
    const float* W_out   = (const float*)d_in[13];
    const float* b_out   = (const float*)d_in[14];
    const float* ln1_g   = (const float*)d_in[15];
    const float* ln1_b   = (const float*)d_in[16];
    const float* W1      = (const float*)d_in[17];
    const float* b1      = (const float*)d_in[18];
    const float* W2      = (const float*)d_in[19];
    const float* b2      = (const float*)d_in[20];
    const float* ln2_g   = (const float*)d_in[21];
    const float* ln2_b   = (const float*)d_in[22];
    float* out = (float*)d_out;

    void *p_valh, *p_Wvalh, *p_vproj, *p_qh, *p_Wfh, *p_bf, *p_Wouth, *p_W1h, *p_W2h;
    void *p_fused, *p_aggh, *p_proj, *p_xh, *p_ffn1h, *p_ffn2;
    cudaGetSymbolAddress(&p_valh,   g_val_h);
    cudaGetSymbolAddress(&p_Wvalh,  g_Wval_h);
    cudaGetSymbolAddress(&p_vproj,  g_vproj);
    cudaGetSymbolAddress(&p_qh,     g_q_h);
    cudaGetSymbolAddress(&p_Wfh,    g_Wf_h);
    cudaGetSymbolAddress(&p_bf,     g_bf);
    cudaGetSymbolAddress(&p_Wouth,  g_Wout_h);
    cudaGetSymbolAddress(&p_W1h,    g_W1_h);
    cudaGetSymbolAddress(&p_W2h,    g_W2_h);
    cudaGetSymbolAddress(&p_fused,  g_fused);
    cudaGetSymbolAddress(&p_aggh,   g_aggh);
    cudaGetSymbolAddress(&p_proj,   g_proj);
    cudaGetSymbolAddress(&p_xh,     g_x_h);
    cudaGetSymbolAddress(&p_ffn1h,  g_ffn1h);
    cudaGetSymbolAddress(&p_ffn2,   g_ffn2);

    static cudaStream_t s2 = nullptr;
    static cudaEvent_t ev_fork = nullptr, ev_join = nullptr;
    if (s2 == nullptr) {
        cudaStreamCreateWithFlags(&s2, cudaStreamNonBlocking);
        cudaEventCreateWithFlags(&ev_fork, cudaEventDisableTiming);
        cudaEventCreateWithFlags(&ev_join, cudaEventDisableTiming);
    }

    // ---- fork: value/W_value conversion + vproj GEMM (bf16 out) on s2 ----
    cudaEventRecord(ev_fork, 0);
    cudaStreamWaitEvent(s2, ev_fork, 0);
    {
        int nconv = (MVAL * CH / 4 + CH * CH / 4 + 255) / 256;
        conv_val_kernel<<<nconv, 256, 0, s2>>>(value, W_value);
        hgemm_bf16<1, __nv_bfloat16><<<dim3(MPAD / 128, CH / 64), 256, 0, s2>>>(
            (const __nv_bfloat16*)p_valh, (const __nv_bfloat16*)p_Wvalh,
            b_value, (__nv_bfloat16*)p_vproj, MPAD, CH, CH);
    }
    cudaEventRecord(ev_join, s2);

    // ---- main stream: prep + fused off/attn GEMM ----
    prep_kernel<<<2585, 256>>>(bev, query, W_off, W_attn, b_off, b_attn,
                               W_out, W1, W2);
    hgemm_bf16<1, float><<<dim3(NQ / 128, NFUS / 64), 256>>>(
        (const __nv_bfloat16*)p_qh, (const __nv_bfloat16*)p_Wfh,
        (const float*)p_bf, (float*)p_fused, NQ, NFUS, CH);

    // ---- join, then sampling ----
    cudaStreamWaitEvent(0, ev_join, 0);
    sample_kernel<<<NQ, 256>>>(refpts);

    // output projection: agg(bf16) @ W_out (bias folded into ln1)
    hgemm_bf16<0, float><<<dim3(NQ / 128, CH / 64), 256>>>(
        (const __nv_bfloat16*)p_aggh, (const __nv_bfloat16*)p_Wouth,
        nullptr, (float*)p_proj, NQ, CH, CH);

    // slots + residual + LN1
    ln1_kernel<<<NQ, 256>>>(query, b_out, ln1_g, ln1_b);

    // FFN up: relu(x @ W1 + b1) -> bf16
    hgemm_bf16<2, __nv_bfloat16><<<dim3(NQ / 128, DFFN / 64), 256>>>(
        (const __nv_bfloat16*)p_xh, (const __nv_bfloat16*)p_W1h,
        b1, (__nv_bfloat16*)p_ffn1h, NQ, DFFN, CH);

    // FFN down: ffn1(bf16) @ W2 + b2
    hgemm_bf16<1, float><<<dim3(NQ / 128, CH / 64), 256>>>(
        (const __nv_bfloat16*)p_ffn1h, (const __nv_bfloat16*)p_W2h,
        b2, (float*)p_ffn2, NQ, CH, DFFN);

    // residual + LN2 -> out
    ln2_kernel<<<NQ, 256>>>(ln2_g, ln2_b, out);

    (void)in_sizes; (void)n_in; (void)out_size;
}

// round 15
// speedup vs baseline: 1.1261x; 1.0200x over previous
#include <cuda_runtime.h>
#include <cuda_bf16.h>
#include <stdint.h>

// Problem constants (fixed by setup_inputs)
#define NQ   6400
#define CAMS 6
#define LTOT 7979
#define CH   256
#define DFFN 1024
#define NFUS 384   // fused off(256) + attn-logits(128)
#define MVAL (CAMS * LTOT)   // 47874
#define MPAD 48000           // 375 * 128

typedef unsigned long long u64;

// ---------------- scratch (static device globals; no allocation) ----------------
__device__ __nv_bfloat16 g_val_h[MPAD * CH];        // value in bf16 (padded rows stay 0)
__device__ __nv_bfloat16 g_Wval_h[CH * CH];         // W_value bf16
__device__ __nv_bfloat16 g_vproj[MPAD * CH];        // value @ W_value + b (bf16)
__device__ __nv_bfloat16 g_q_h[NQ * CH];            // query in bf16
__device__ __nv_bfloat16 g_Wf_h[CH * NFUS];         // fused [W_off | W_attn] bf16
__device__ float g_bf[NFUS];                        // fused bias (fp32)
__device__ __nv_bfloat16 g_Wout_h[CH * CH];         // W_out bf16
__device__ __nv_bfloat16 g_W1_h[CH * DFFN];         // W1 bf16
__device__ __nv_bfloat16 g_W2_h[DFFN * CH];         // W2 bf16
__device__ float g_fused[NQ * NFUS];                // fused offsets + attn logits
__device__ __nv_bfloat16 g_aggh[NQ * CH];           // aggregated samples (bf16)
__device__ float g_proj[NQ * CH];                   // agg @ W_out
__device__ float g_x[NQ * CH];                      // after LN1 (fp32)
__device__ __nv_bfloat16 g_x_h[NQ * CH];            // after LN1 (bf16)
__device__ __nv_bfloat16 g_ffn1h[NQ * DFFN];        // relu(x@W1+b1) (bf16)
__device__ float g_ffn2[NQ * CH];                   // ffn1@W2+b2
__device__ unsigned int g_vis[NQ];                  // camera visibility bitmask
__device__ float g_cnt[NQ];                         // number of visible cameras

__constant__ int c_W[4] = {100, 50, 25, 13};
__constant__ int c_H[4] = {60, 30, 15, 8};
__constant__ int c_S[4] = {0, 6000, 7500, 7875};

// ---------------- f32x2 packed-math helpers ----------------
__device__ __forceinline__ u64 pkf2(float lo, float hi) {
    u64 r; asm("mov.b64 %0, {%1, %2};" : "=l"(r) : "f"(lo), "f"(hi)); return r;
}
__device__ __forceinline__ u64 bf2f2(uint32_t v) {
    uint32_t lo = v << 16, hi = v & 0xFFFF0000u;
    u64 r; asm("mov.b64 %0, {%1, %2};" : "=l"(r) : "r"(lo), "r"(hi)); return r;
}
__device__ __forceinline__ void ffma2(u64& d, u64 a, u64 b) {
    asm("fma.rn.f32x2 %0, %1, %2, %0;" : "+l"(d) : "l"(a), "l"(b));
}
__device__ __forceinline__ float2 upk(u64 v) {
    float2 f; asm("mov.b64 {%0, %1}, %2;" : "=f"(f.x), "=f"(f.y) : "l"(v)); return f;
}
// Predicated 16B global load: executes only when doit != 0; otherwise q keeps
// its previous contents (outputs are read-write).
__device__ __forceinline__ void ldg128_pred(uint4& q, const __nv_bfloat16* p, int doit) {
    asm volatile("{\n\t"
        ".reg .pred pp;\n\t"
        "setp.ne.s32 pp, %5, 0;\n\t"
        "@pp ld.global.nc.v4.u32 {%0,%1,%2,%3}, [%4];\n\t"
        "}"
        : "+r"(q.x), "+r"(q.y), "+r"(q.z), "+r"(q.w)
        : "l"(p), "r"(doit));
}

// ---------------- fused prep: mask + query/weight fp32->bf16 ----------------
__global__ __launch_bounds__(256) void prep_kernel(
    const int* __restrict__ bev, const float* __restrict__ query,
    const float* __restrict__ Woff, const float* __restrict__ Wattn,
    const float* __restrict__ boff, const float* __restrict__ battn,
    const float* __restrict__ Wout, const float* __restrict__ W1,
    const float* __restrict__ W2)
{
    const int b = blockIdx.x, tid = threadIdx.x;
    if (b < 25) {
        int n = b * 256 + tid;
        unsigned int vm = 0; int cnt = 0;
        #pragma unroll
        for (int k = 0; k < CAMS; k++) {
            const int* bp = bev + ((size_t)k * NQ + n) * 4;
            if (bp[0] + bp[1] + bp[2] + bp[3] > 0) { vm |= (1u << k); cnt++; }
        }
        g_vis[n] = vm;
        g_cnt[n] = (float)cnt;
    } else if (b < 1625) {
        int i = (b - 25) * 256 + tid;           // float4 index, < 409600
        float4 v = ((const float4*)query)[i];
        ((__nv_bfloat162*)g_q_h)[i * 2]     = __floats2bfloat162_rn(v.x, v.y);
        ((__nv_bfloat162*)g_q_h)[i * 2 + 1] = __floats2bfloat162_rn(v.z, v.w);
    } else if (b < 2009) {
        int i = (b - 1625) * 256 + tid;         // < 98304
        int k = i / NFUS, n = i % NFUS;
        float v = (n < 256) ? Woff[k * 256 + n] : Wattn[k * 128 + (n - 256)];
        g_Wf_h[i] = __float2bfloat16_rn(v);
        if (i < NFUS) g_bf[i] = (i < 256) ? boff[i] : battn[i - 256];
    } else if (b < 2073) {
        int i = (b - 2009) * 256 + tid;         // < 16384
        float4 v = ((const float4*)Wout)[i];
        ((__nv_bfloat162*)g_Wout_h)[i * 2]     = __floats2bfloat162_rn(v.x, v.y);
        ((__nv_bfloat162*)g_Wout_h)[i * 2 + 1] = __floats2bfloat162_rn(v.z, v.w);
    } else if (b < 2329) {
        int i = (b - 2073) * 256 + tid;         // < 65536
        float4 v = ((const float4*)W1)[i];
        ((__nv_bfloat162*)g_W1_h)[i * 2]     = __floats2bfloat162_rn(v.x, v.y);
        ((__nv_bfloat162*)g_W1_h)[i * 2 + 1] = __floats2bfloat162_rn(v.z, v.w);
    } else {
        int i = (b - 2329) * 256 + tid;         // < 65536
        float4 v = ((const float4*)W2)[i];
        ((__nv_bfloat162*)g_W2_h)[i * 2]     = __floats2bfloat162_rn(v.x, v.y);
        ((__nv_bfloat162*)g_W2_h)[i * 2 + 1] = __floats2bfloat162_rn(v.z, v.w);
    }
}

// ---------------- value + W_value fp32 -> bf16 (stream 2) ----------------
__global__ __launch_bounds__(256) void conv_val_kernel(
    const float* __restrict__ val, const float* __restrict__ Wv)
{
    const int NV = MVAL * CH / 4;   // 3,063,936
    int i = blockIdx.x * 256 + threadIdx.x;
    if (i < NV) {
        float4 v = ((const float4*)val)[i];
        ((__nv_bfloat162*)g_val_h)[i * 2]     = __floats2bfloat162_rn(v.x, v.y);
        ((__nv_bfloat162*)g_val_h)[i * 2 + 1] = __floats2bfloat162_rn(v.z, v.w);
    } else {
        int j = i - NV;
        if (j < CH * CH / 4) {
            float4 v = ((const float4*)Wv)[j];
            ((__nv_bfloat162*)g_Wval_h)[j * 2]     = __floats2bfloat162_rn(v.x, v.y);
            ((__nv_bfloat162*)g_Wval_h)[j * 2 + 1] = __floats2bfloat162_rn(v.z, v.w);
        }
    }
}

// ---------------- tensor-core GEMM building blocks ----------------
__device__ __forceinline__ void ldsm4(uint32_t* r, const void* p) {
    uint32_t a = (uint32_t)__cvta_generic_to_shared(p);
    asm volatile("ldmatrix.sync.aligned.m8n8.x4.shared.b16 {%0,%1,%2,%3}, [%4];"
                 : "=r"(r[0]), "=r"(r[1]), "=r"(r[2]), "=r"(r[3]) : "r"(a));
}
__device__ __forceinline__ void ldsm4t(uint32_t* r, const void* p) {
    uint32_t a = (uint32_t)__cvta_generic_to_shared(p);
    asm volatile("ldmatrix.sync.aligned.m8n8.x4.trans.shared.b16 {%0,%1,%2,%3}, [%4];"
                 : "=r"(r[0]), "=r"(r[1]), "=r"(r[2]), "=r"(r[3]) : "r"(a));
}
__device__ __forceinline__ void mma_bf16(float* d, const uint32_t* a, const uint32_t* b) {
    asm volatile("mma.sync.aligned.m16n8k16.row.col.f32.bf16.bf16.f32 "
                 "{%0,%1,%2,%3}, {%4,%5,%6,%7}, {%8,%9}, {%0,%1,%2,%3};"
                 : "+f"(d[0]), "+f"(d[1]), "+f"(d[2]), "+f"(d[3])
                 : "r"(a[0]), "r"(a[1]), "r"(a[2]), "r"(a[3]), "r"(b[0]), "r"(b[1]));
}
__device__ __forceinline__ void cpa16(void* dst, const void* src) {
    uint32_t d = (uint32_t)__cvta_generic_to_shared(dst);
    asm volatile("cp.async.cg.shared.global [%0], [%1], 16;" :: "r"(d), "l"(src));
}
__device__ __forceinline__ void store2(float* C, float x, float y) {
    *(float2*)C = make_float2(x, y);
}
__device__ __forceinline__ void store2(__nv_bfloat16* C, float x, float y) {
    *(__nv_bfloat162*)C = __floats2bfloat162_rn(x, y);
}

// ================== bf16 cp.async GEMM ==================
// C(MxN) = A(MxK,bf16 rm) * B(KxN,bf16 rm) (+bias)(+relu). 128x64 tile, BK=32,
// 4-stage cp.async, 256 thr (8 warps x 32x32). M%128==0, N%64==0, K%32==0.
#define STAGES 4
template<int EPI, typename OutT>
__global__ __launch_bounds__(256, 2) void hgemm_bf16(
    const __nv_bfloat16* __restrict__ A, const __nv_bfloat16* __restrict__ B,
    const float* __restrict__ bias, OutT* __restrict__ C,
    int M, int N, int K)
{
    __shared__ __align__(16) __nv_bfloat16 As[STAGES][128][40];
    __shared__ __align__(16) __nv_bfloat16 Bs[STAGES][32][72];   // [k][n]
    const int tid = threadIdx.x;
    const int bm = blockIdx.x * 128, bn = blockIdx.y * 64;
    const int lane = tid & 31, w = tid >> 5;
    const int m0 = (w >> 1) * 32, n0 = (w & 1) * 32;

    float acc[2][4][4];
    #pragma unroll
    for (int i = 0; i < 2; i++)
        #pragma unroll
        for (int j = 0; j < 4; j++)
            #pragma unroll
            for (int l = 0; l < 4; l++) acc[i][j][l] = 0.0f;

    const int arow = tid >> 1, acol = (tid & 1) * 16;
    const int brow = tid >> 3, bcol = (tid & 7) * 8;

    const __nv_bfloat16* Asrc = A + (size_t)(bm + arow) * K + acol;
    const __nv_bfloat16* Bsrc = B + bn + bcol;

    const int KT = K >> 5;

#define ISSUE(s, kt) do {                                                      \
    cpa16(&As[s][arow][acol],     Asrc + (kt) * 32);                           \
    cpa16(&As[s][arow][acol + 8], Asrc + (kt) * 32 + 8);                       \
    cpa16(&Bs[s][brow][bcol],     Bsrc + (size_t)((kt) * 32 + brow) * N);      \
} while (0)

#define COMPUTE_T(b) do {                                                      \
    _Pragma("unroll")                                                          \
    for (int ks = 0; ks < 2; ks++) {                                           \
        uint32_t af[2][4], bfr[4][2];                                          \
        _Pragma("unroll")                                                      \
        for (int mt = 0; mt < 2; mt++)                                         \
            ldsm4(af[mt], &As[b][m0 + mt * 16 + (lane & 15)]                   \
                             [ks * 16 + ((lane >> 4) << 3)]);                  \
        _Pragma("unroll")                                                      \
        for (int nt2 = 0; nt2 < 2; nt2++) {                                    \
            uint32_t t[4];                                                     \
            ldsm4t(t, &Bs[b][ks * 16 + (lane & 7) + 8 * ((lane >> 3) & 1)]     \
                            [n0 + nt2 * 16 + 8 * (lane >> 4)]);                \
            bfr[nt2 * 2][0] = t[0];      bfr[nt2 * 2][1] = t[1];               \
            bfr[nt2 * 2 + 1][0] = t[2];  bfr[nt2 * 2 + 1][1] = t[3];           \
        }                                                                      \
        _Pragma("unroll")                                                      \
        for (int mt = 0; mt < 2; mt++)                                         \
            _Pragma("unroll")                                                  \
            for (int nt = 0; nt < 4; nt++)                                     \
                mma_bf16(acc[mt][nt], af[mt], bfr[nt]);                        \
    }                                                                          \
} while (0)

    #pragma unroll
    for (int s = 0; s < STAGES - 1; s++) {
        if (s < KT) ISSUE(s, s);
        asm volatile("cp.async.commit_group;");
    }

    for (int kt = 0; kt < KT; kt++) {
        asm volatile("cp.async.wait_group %0;" :: "n"(STAGES - 2));
        __syncthreads();
        int kn = kt + STAGES - 1;
        if (kn < KT) ISSUE(kn & (STAGES - 1), kn);
        asm volatile("cp.async.commit_group;");
        COMPUTE_T(kt & (STAGES - 1));
    }
#undef ISSUE
#undef COMPUTE_T

    const int row0 = bm + m0 + (lane >> 2);
    #pragma unroll
    for (int mt = 0; mt < 2; mt++) {
        int r0 = row0 + mt * 16, r1 = r0 + 8;
        #pragma unroll
        for (int nt = 0; nt < 4; nt++) {
            int col = bn + n0 + nt * 8 + ((lane & 3) << 1);
            float b0 = 0.f, b1 = 0.f;
            if (EPI >= 1) { b0 = __ldg(bias + col); b1 = __ldg(bias + col + 1); }
            float v0 = acc[mt][nt][0] + b0, v1 = acc[mt][nt][1] + b1;
            float v2 = acc[mt][nt][2] + b0, v3 = acc[mt][nt][3] + b1;
            if (EPI == 2) {
                v0 = fmaxf(v0, 0.f); v1 = fmaxf(v1, 0.f);
                v2 = fmaxf(v2, 0.f); v3 = fmaxf(v3, 0.f);
            }
            store2(C + (size_t)r0 * N + col, v0, v1);
            store2(C + (size_t)r1 * N + col, v2, v3);
        }
    }
}

// ---------------- deformable sampling + cross-camera aggregation ----------------
// R8 phases 0/1 unchanged. Phase 2 remapped: warp = (level, cam-triple); each
// warp walks 4 consecutive points of its level per camera, comparing corner
// indices to the previous point's — identical corners skip the 4 gathers via
// predicated loads (bit-identical results; predicated-off lanes cost no L1
// wavefronts). FFMAs always execute with their own weights.
__global__ __launch_bounds__(256) void sample_kernel(
    const float* __restrict__ ref)   // (6, 6400, 4, 2)
{
    __shared__ float4 sw[768];
    __shared__ int4 sidx[768];
    __shared__ float saw[128];
    __shared__ float4 sred[256][2];
    const int n = blockIdx.x;
    const int tid = threadIdx.x;
    const unsigned int vism = g_vis[n];

    // Phase 0: softmax over each 16-point group (8 heads)
    if (tid < 128) {
        float lv = g_fused[(size_t)n * NFUS + 256 + tid];
        float mx = lv;
        #pragma unroll
        for (int o = 8; o > 0; o >>= 1)
            mx = fmaxf(mx, __shfl_xor_sync(0xffffffffu, mx, o));
        float e = expf(lv - mx);
        float s = e;
        #pragma unroll
        for (int o = 8; o > 0; o >>= 1)
            s += __shfl_xor_sync(0xffffffffu, s, o);
        saw[tid] = e / s;
    }
    __syncthreads();

    // Phase 1: weights + corner row indices
    #pragma unroll
    for (int t = 0; t < 3; t++) {
        int cid = tid + t * 256;
        int k = cid >> 7;
        int r = cid & 127;          // h*16 + lvl*4 + p
        int h = r >> 4;
        int lvl = (r >> 2) & 3;
        int p = r & 3;
        float4 wv = make_float4(0.f, 0.f, 0.f, 0.f);
        int4 iv = make_int4(0, 0, 0, 0);
        if ((vism >> k) & 1) {
            int Wi = c_W[lvl], Hi = c_H[lvl];
            float Wf = (float)Wi, Hf = (float)Hi;
            const float* rp = ref + (((size_t)k * NQ + n) * 4 + lvl) * 2;
            float rx = rp[0], ry = rp[1];
            int oi = ((h * 4 + lvl) * 4 + p) * 2;
            float ox = g_fused[(size_t)n * NFUS + oi];
            float oy = g_fused[(size_t)n * NFUS + oi + 1];
            float x = (rx + ox / Wf) * Wf - 0.5f;
            float y = (ry + oy / Hf) * Hf - 0.5f;
            float x0f = floorf(x), y0f = floorf(y);
            float lx = x - x0f, ly = y - y0f;
            int x0 = (int)x0f, y0 = (int)y0f;
            float a = saw[r];
            bool vx0 = (x0 >= 0) && (x0 < Wi);
            bool vx1 = (x0 + 1 >= 0) && (x0 + 1 < Wi);
            bool vy0 = (y0 >= 0) && (y0 < Hi);
            bool vy1 = (y0 + 1 >= 0) && (y0 + 1 < Hi);
            float omx = 1.0f - lx, omy = 1.0f - ly;
            wv.x = (vx0 && vy0) ? a * omx * omy : 0.0f;
            wv.y = (vx1 && vy0) ? a * lx * omy : 0.0f;
            wv.z = (vx0 && vy1) ? a * omx * ly : 0.0f;
            wv.w = (vx1 && vy1) ? a * lx * ly : 0.0f;
            int xc0 = min(max(x0, 0), Wi - 1);
            int xc1 = min(max(x0 + 1, 0), Wi - 1);
            int yc0 = min(max(y0, 0), Hi - 1);
            int yc1 = min(max(y0 + 1, 0), Hi - 1);
            int rb = k * LTOT + c_S[lvl];
            int r0 = rb + yc0 * Wi, r1 = rb + yc1 * Wi;
            iv = make_int4(r0 + xc0, r0 + xc1, r1 + xc0, r1 + xc1);
        }
        sw[cid] = wv;
        sidx[cid] = iv;
    }
    __syncthreads();

    // Phase 2: warp = (level, cam-triple); chain corner-reuse across points.
    const int cg = tid & 31;              // 8-channel group
    const int hh = cg >> 2;               // head
    const int w5 = tid >> 5;              // warp id 0..7
    const int lvl = w5 & 3;               // level handled by this warp
    const int kb = (w5 >> 2) * 3;         // cams {0,1,2} or {3,4,5}
    const __nv_bfloat16* vb = g_vproj + cg * 8;
    u64 a0 = 0, a1 = 0, a2 = 0, a3 = 0;

    #pragma unroll 1
    for (int c = 0; c < 3; c++) {
        const int k = kb + c;
        if (!((vism >> k) & 1)) continue;
        const int base = k * 128 + hh * 16 + lvl * 4;
        int4 ivp = make_int4(-1, -1, -1, -1);
        uint4 q0 = make_uint4(0, 0, 0, 0), q1 = q0, q2 = q0, q3 = q0;
        #pragma unroll
        for (int p = 0; p < 4; p++) {
            float4 w = sw[base + p];
            int4 iv = sidx[base + p];
            int diff = (iv.x ^ ivp.x) | (iv.y ^ ivp.y) |
                       (iv.z ^ ivp.z) | (iv.w ^ ivp.w);
            ldg128_pred(q0, vb + ((size_t)iv.x << 8), diff);
            ldg128_pred(q1, vb + ((size_t)iv.y << 8), diff);
            ldg128_pred(q2, vb + ((size_t)iv.z << 8), diff);
            ldg128_pred(q3, vb + ((size_t)iv.w << 8), diff);
            ivp = iv;
            u64 w0 = pkf2(w.x, w.x), w1 = pkf2(w.y, w.y);
            u64 w2 = pkf2(w.z, w.z), w3 = pkf2(w.w, w.w);
            ffma2(a0, w0, bf2f2(q0.x)); ffma2(a1, w0, bf2f2(q0.y));
            ffma2(a2, w0, bf2f2(q0.z)); ffma2(a3, w0, bf2f2(q0.w));
            ffma2(a0, w1, bf2f2(q1.x)); ffma2(a1, w1, bf2f2(q1.y));
            ffma2(a2, w1, bf2f2(q1.z)); ffma2(a3, w1, bf2f2(q1.w));
            ffma2(a0, w2, bf2f2(q2.x)); ffma2(a1, w2, bf2f2(q2.y));
            ffma2(a2, w2, bf2f2(q2.z)); ffma2(a3, w2, bf2f2(q2.w));
            ffma2(a0, w3, bf2f2(q3.x)); ffma2(a1, w3, bf2f2(q3.y));
            ffma2(a2, w3, bf2f2(q3.z)); ffma2(a3, w3, bf2f2(q3.w));
        }
    }

    float2 f0 = upk(a0), f1 = upk(a1), f2 = upk(a2), f3 = upk(a3);
    sred[tid][0] = make_float4(f0.x, f0.y, f1.x, f1.y);
    sred[tid][1] = make_float4(f2.x, f2.y, f3.x, f3.y);
    __syncthreads();
    if (tid < 128) {
        float4 x0 = sred[tid + 128][0], x1 = sred[tid + 128][1];
        float4 y0 = sred[tid][0], y1 = sred[tid][1];
        y0.x += x0.x; y0.y += x0.y; y0.z += x0.z; y0.w += x0.w;
        y1.x += x1.x; y1.y += x1.y; y1.z += x1.z; y1.w += x1.w;
        sred[tid][0] = y0; sred[tid][1] = y1;
    }
    __syncthreads();
    if (tid < 64) {
        float4 x0 = sred[tid + 64][0], x1 = sred[tid + 64][1];
        float4 y0 = sred[tid][0], y1 = sred[tid][1];
        y0.x += x0.x; y0.y += x0.y; y0.z += x0.z; y0.w += x0.w;
        y1.x += x1.x; y1.y += x1.y; y1.z += x1.z; y1.w += x1.w;
        sred[tid][0] = y0; sred[tid][1] = y1;
    }
    __syncthreads();
    if (tid < 32) {
        float4 x0 = sred[tid + 32][0], x1 = sred[tid + 32][1];
        float4 y0 = sred[tid][0], y1 = sred[tid][1];
        y0.x += x0.x; y0.y += x0.y; y0.z += x0.z; y0.w += x0.w;
        y1.x += x1.x; y1.y += x1.y; y1.z += x1.z; y1.w += x1.w;
        __nv_bfloat162 p0 = __floats2bfloat162_rn(y0.x, y0.y);
        __nv_bfloat162 p1 = __floats2bfloat162_rn(y0.z, y0.w);
        __nv_bfloat162 p2 = __floats2bfloat162_rn(y1.x, y1.y);
        __nv_bfloat162 p3 = __floats2bfloat162_rn(y1.z, y1.w);
        uint4 pk;
        pk.x = *(uint32_t*)&p0; pk.y = *(uint32_t*)&p1;
        pk.z = *(uint32_t*)&p2; pk.w = *(uint32_t*)&p3;
        *(uint4*)(g_aggh + (size_t)n * CH + tid * 8) = pk;
    }
}

// ---------------- block reduction helper ----------------
__device__ __forceinline__ float blocksum256(float v, float* sh) {
    #pragma unroll
    for (int o = 16; o > 0; o >>= 1) v += __shfl_xor_sync(0xffffffffu, v, o);
    if ((threadIdx.x & 31) == 0) sh[threadIdx.x >> 5] = v;
    __syncthreads();
    float s = 0.f;
    #pragma unroll
    for (int i = 0; i < 8; i++) s += sh[i];
    __syncthreads();
    return s;
}

// ---------------- slots assembly + residual + LN1 ----------------
__global__ __launch_bounds__(256) void ln1_kernel(
    const float* __restrict__ query, const float* __restrict__ b_out,
    const float* __restrict__ gamma, const float* __restrict__ beta)
{
    __shared__ float sh[8];
    const int n = blockIdx.x, c = threadIdx.x;
    float m = g_cnt[n];
    float q = query[(size_t)n * CH + c];
    float s = m * (q + b_out[c]) + g_proj[(size_t)n * CH + c];
    float t = s / fmaxf(m, 1.0f) + q;
    float mu = blocksum256(t, sh) * (1.0f / CH);
    float d = t - mu;
    float var = blocksum256(d * d, sh) * (1.0f / CH);
    float xv = d * rsqrtf(var + 1e-5f) * gamma[c] + beta[c];
    g_x[(size_t)n * CH + c] = xv;
    g_x_h[(size_t)n * CH + c] = __float2bfloat16_rn(xv);
}

// ---------------- FFN residual + LN2 -> output ----------------
__global__ __launch_bounds__(256) void ln2_kernel(
    const float* __restrict__ gamma, const float* __restrict__ beta,
    float* __restrict__ out)
{
    __shared__ float sh[8];
    const int n = blockIdx.x, c = threadIdx.x;
    float t = g_x[(size_t)n * CH + c] + g_ffn2[(size_t)n * CH + c];
    float mu = blocksum256(t, sh) * (1.0f / CH);
    float d = t - mu;
    float var = blocksum256(d * d, sh) * (1.0f / CH);
    out[(size_t)n * CH + c] = d * rsqrtf(var + 1e-5f) * gamma[c] + beta[c];
}

// ---------------- host launcher ----------------
extern "C" void kernel_launch(void* const* d_in, const int* in_sizes, int n_in,
                              void* d_out, int out_size) {
    const float* query   = (const float*)d_in[0];
    const float* value   = (const float*)d_in[2];
    const float* refpts  = (const float*)d_in[3];
    const int*   bev     = (const int*)d_in[6];
    const float* W_value = (const float*)d_in[7];
    const float* b_value = (const float*)d_in[8];
    const float* W_off   = (const float*)d_in[9];
    const float* b_off   = (const float*)d_in[10];
    const float* W_attn  = (const float*)d_in[11];
    const float* b_attn  = (const float*)d_in[12];
    const float* W_out   = (const float*)d_in[13];
    const float* b_out   = (const float*)d_in[14];
    const float* ln1_g   = (const float*)d_in[15];
    const float* ln1_b   = (const float*)d_in[16];
    const float* W1      = (const float*)d_in[17];
    const float* b1      = (const float*)d_in[18];
    const float* W2      = (const float*)d_in[19];
    const float* b2      = (const float*)d_in[20];
    const float* ln2_g   = (const float*)d_in[21];
    const float* ln2_b   = (const float*)d_in[22];
    float* out = (float*)d_out;

    void *p_valh, *p_Wvalh, *p_vproj, *p_qh, *p_Wfh, *p_bf, *p_Wouth, *p_W1h, *p_W2h;
    void *p_fused, *p_aggh, *p_proj, *p_xh, *p_ffn1h, *p_ffn2;
    cudaGetSymbolAddress(&p_valh,   g_val_h);
    cudaGetSymbolAddress(&p_Wvalh,  g_Wval_h);
    cudaGetSymbolAddress(&p_vproj,  g_vproj);
    cudaGetSymbolAddress(&p_qh,     g_q_h);
    cudaGetSymbolAddress(&p_Wfh,    g_Wf_h);
    cudaGetSymbolAddress(&p_bf,     g_bf);
    cudaGetSymbolAddress(&p_Wouth,  g_Wout_h);
    cudaGetSymbolAddress(&p_W1h,    g_W1_h);
    cudaGetSymbolAddress(&p_W2h,    g_W2_h);
    cudaGetSymbolAddress(&p_fused,  g_fused);
    cudaGetSymbolAddress(&p_aggh,   g_aggh);
    cudaGetSymbolAddress(&p_proj,   g_proj);
    cudaGetSymbolAddress(&p_xh,     g_x_h);
    cudaGetSymbolAddress(&p_ffn1h,  g_ffn1h);
    cudaGetSymbolAddress(&p_ffn2,   g_ffn2);

    static cudaStream_t s2 = nullptr;
    static cudaEvent_t ev_fork = nullptr, ev_join = nullptr;
    if (s2 == nullptr) {
        cudaStreamCreateWithFlags(&s2, cudaStreamNonBlocking);
        cudaEventCreateWithFlags(&ev_fork, cudaEventDisableTiming);
        cudaEventCreateWithFlags(&ev_join, cudaEventDisableTiming);
    }

    // ---- fork: value/W_value conversion + vproj GEMM (bf16 out) on s2 ----
    cudaEventRecord(ev_fork, 0);
    cudaStreamWaitEvent(s2, ev_fork, 0);
    {
        int nconv = (MVAL * CH / 4 + CH * CH / 4 + 255) / 256;
        conv_val_kernel<<<nconv, 256, 0, s2>>>(value, W_value);
        hgemm_bf16<1, __nv_bfloat16><<<dim3(MPAD / 128, CH / 64), 256, 0, s2>>>(
            (const __nv_bfloat16*)p_valh, (const __nv_bfloat16*)p_Wvalh,
            b_value, (__nv_bfloat16*)p_vproj, MPAD, CH, CH);
    }
    cudaEventRecord(ev_join, s2);

    // ---- main stream: prep + fused off/attn GEMM ----
    prep_kernel<<<2585, 256>>>(bev, query, W_off, W_attn, b_off, b_attn,
                               W_out, W1, W2);
    hgemm_bf16<1, float><<<dim3(NQ / 128, NFUS / 64), 256>>>(
        (const __nv_bfloat16*)p_qh, (const __nv_bfloat16*)p_Wfh,
        (const float*)p_bf, (float*)p_fused, NQ, NFUS, CH);

    // ---- join, then sampling ----
    cudaStreamWaitEvent(0, ev_join, 0);
    sample_kernel<<<NQ, 256>>>(refpts);

    // output projection: agg(bf16) @ W_out (bias folded into ln1)
    hgemm_bf16<0, float><<<dim3(NQ / 128, CH / 64), 256>>>(
        (const __nv_bfloat16*)p_aggh, (const __nv_bfloat16*)p_Wouth,
        nullptr, (float*)p_proj, NQ, CH, CH);

    // slots + residual + LN1
    ln1_kernel<<<NQ, 256>>>(query, b_out, ln1_g, ln1_b);

    // FFN up: relu(x @ W1 + b1) -> bf16
    hgemm_bf16<2, __nv_bfloat16><<<dim3(NQ / 128, DFFN / 64), 256>>>(
        (const __nv_bfloat16*)p_xh, (const __nv_bfloat16*)p_W1h,
        b1, (__nv_bfloat16*)p_ffn1h, NQ, DFFN, CH);

    // FFN down: ffn1(bf16) @ W2 + b2
    hgemm_bf16<1, float><<<dim3(NQ / 128, CH / 64), 256>>>(
        (const __nv_bfloat16*)p_ffn1h, (const __nv_bfloat16*)p_W2h,
        b2, (float*)p_ffn2, NQ, CH, DFFN);

    // residual + LN2 -> out
    ln2_kernel<<<NQ, 256>>>(ln2_g, ln2_b, out);

    (void)in_sizes; (void)n_in; (void)out_size;
}

// round 16
// speedup vs baseline: 1.1553x; 1.0260x over previous
#include <cuda_runtime.h>
#include <cuda_bf16.h>
#include <stdint.h>

// Problem constants (fixed by setup_inputs)
#define NQ   6400
#define CAMS 6
#define LTOT 7979
#define CH   256
#define DFFN 1024
#define NFUS 384   // fused off(256) + attn-logits(128)
#define MVAL (CAMS * LTOT)   // 47874
#define MPAD 48000           // 375 * 128

typedef unsigned long long u64;

// ---------------- scratch (static device globals; no allocation) ----------------
__device__ __nv_bfloat16 g_val_h[MPAD * CH];        // value in bf16 (padded rows stay 0)
__device__ __nv_bfloat16 g_Wval_h[CH * CH];         // W_value bf16
__device__ __nv_bfloat16 g_vproj[MPAD * CH];        // value @ W_value + b (bf16)
__device__ __nv_bfloat16 g_q_h[NQ * CH];            // query in bf16
__device__ __nv_bfloat16 g_Wf_h[CH * NFUS];         // fused [W_off | W_attn] bf16
__device__ float g_bf[NFUS];                        // fused bias (fp32)
__device__ __nv_bfloat16 g_Wout_h[CH * CH];         // W_out bf16
__device__ __nv_bfloat16 g_W1_h[CH * DFFN];         // W1 bf16
__device__ __nv_bfloat16 g_W2_h[DFFN * CH];         // W2 bf16
__device__ float g_fused[NQ * NFUS];                // fused offsets + attn logits
__device__ __nv_bfloat16 g_aggh[NQ * CH];           // aggregated samples (bf16)
__device__ float g_proj[NQ * CH];                   // agg @ W_out
__device__ float g_x[NQ * CH];                      // after LN1 (fp32)
__device__ __nv_bfloat16 g_x_h[NQ * CH];            // after LN1 (bf16)
__device__ __nv_bfloat16 g_ffn1h[NQ * DFFN];        // relu(x@W1+b1) (bf16)
__device__ float g_ffn2[NQ * CH];                   // ffn1@W2+b2
__device__ unsigned int g_vis[NQ];                  // camera visibility bitmask
__device__ float g_cnt[NQ];                         // number of visible cameras

__constant__ int c_W[4] = {100, 50, 25, 13};
__constant__ int c_H[4] = {60, 30, 15, 8};
__constant__ int c_S[4] = {0, 6000, 7500, 7875};

// ---------------- f32x2 packed-math helpers ----------------
__device__ __forceinline__ u64 pkf2(float lo, float hi) {
    u64 r; asm("mov.b64 %0, {%1, %2};" : "=l"(r) : "f"(lo), "f"(hi)); return r;
}
__device__ __forceinline__ u64 bf2f2(uint32_t v) {
    uint32_t lo = v << 16, hi = v & 0xFFFF0000u;
    u64 r; asm("mov.b64 %0, {%1, %2};" : "=l"(r) : "r"(lo), "r"(hi)); return r;
}
__device__ __forceinline__ void ffma2(u64& d, u64 a, u64 b) {
    asm("fma.rn.f32x2 %0, %1, %2, %0;" : "+l"(d) : "l"(a), "l"(b));
}
__device__ __forceinline__ float2 upk(u64 v) {
    float2 f; asm("mov.b64 {%0, %1}, %2;" : "=f"(f.x), "=f"(f.y) : "l"(v)); return f;
}
// Predicated 16B global load (uniform predicate per warp here): only executes
// when doit != 0, else q keeps previous contents.
__device__ __forceinline__ void ldg128_pred(uint4& q, const __nv_bfloat16* p, int doit) {
    asm volatile("{\n\t"
        ".reg .pred pp;\n\t"
        "setp.ne.s32 pp, %5, 0;\n\t"
        "@pp ld.global.nc.v4.u32 {%0,%1,%2,%3}, [%4];\n\t"
        "}"
        : "+r"(q.x), "+r"(q.y), "+r"(q.z), "+r"(q.w)
        : "l"(p), "r"(doit));
}

// ---------------- fused prep: mask + query/weight fp32->bf16 ----------------
__global__ __launch_bounds__(256) void prep_kernel(
    const int* __restrict__ bev, const float* __restrict__ query,
    const float* __restrict__ Woff, const float* __restrict__ Wattn,
    const float* __restrict__ boff, const float* __restrict__ battn,
    const float* __restrict__ Wout, const float* __restrict__ W1,
    const float* __restrict__ W2)
{
    const int b = blockIdx.x, tid = threadIdx.x;
    if (b < 25) {
        int n = b * 256 + tid;
        unsigned int vm = 0; int cnt = 0;
        #pragma unroll
        for (int k = 0; k < CAMS; k++) {
            const int* bp = bev + ((size_t)k * NQ + n) * 4;
            if (bp[0] + bp[1] + bp[2] + bp[3] > 0) { vm |= (1u << k); cnt++; }
        }
        g_vis[n] = vm;
        g_cnt[n] = (float)cnt;
    } else if (b < 1625) {
        int i = (b - 25) * 256 + tid;           // float4 index, < 409600
        float4 v = ((const float4*)query)[i];
        ((__nv_bfloat162*)g_q_h)[i * 2]     = __floats2bfloat162_rn(v.x, v.y);
        ((__nv_bfloat162*)g_q_h)[i * 2 + 1] = __floats2bfloat162_rn(v.z, v.w);
    } else if (b < 2009) {
        int i = (b - 1625) * 256 + tid;         // < 98304
        int k = i / NFUS, n = i % NFUS;
        float v = (n < 256) ? Woff[k * 256 + n] : Wattn[k * 128 + (n - 256)];
        g_Wf_h[i] = __float2bfloat16_rn(v);
        if (i < NFUS) g_bf[i] = (i < 256) ? boff[i] : battn[i - 256];
    } else if (b < 2073) {
        int i = (b - 2009) * 256 + tid;         // < 16384
        float4 v = ((const float4*)Wout)[i];
        ((__nv_bfloat162*)g_Wout_h)[i * 2]     = __floats2bfloat162_rn(v.x, v.y);
        ((__nv_bfloat162*)g_Wout_h)[i * 2 + 1] = __floats2bfloat162_rn(v.z, v.w);
    } else if (b < 2329) {
        int i = (b - 2073) * 256 + tid;         // < 65536
        float4 v = ((const float4*)W1)[i];
        ((__nv_bfloat162*)g_W1_h)[i * 2]     = __floats2bfloat162_rn(v.x, v.y);
        ((__nv_bfloat162*)g_W1_h)[i * 2 + 1] = __floats2bfloat162_rn(v.z, v.w);
    } else {
        int i = (b - 2329) * 256 + tid;         // < 65536
        float4 v = ((const float4*)W2)[i];
        ((__nv_bfloat162*)g_W2_h)[i * 2]     = __floats2bfloat162_rn(v.x, v.y);
        ((__nv_bfloat162*)g_W2_h)[i * 2 + 1] = __floats2bfloat162_rn(v.z, v.w);
    }
}

// ---------------- value + W_value fp32 -> bf16 (stream 2) ----------------
__global__ __launch_bounds__(256) void conv_val_kernel(
    const float* __restrict__ val, const float* __restrict__ Wv)
{
    const int NV = MVAL * CH / 4;   // 3,063,936
    int i = blockIdx.x * 256 + threadIdx.x;
    if (i < NV) {
        float4 v = ((const float4*)val)[i];
        ((__nv_bfloat162*)g_val_h)[i * 2]     = __floats2bfloat162_rn(v.x, v.y);
        ((__nv_bfloat162*)g_val_h)[i * 2 + 1] = __floats2bfloat162_rn(v.z, v.w);
    } else {
        int j = i - NV;
        if (j < CH * CH / 4) {
            float4 v = ((const float4*)Wv)[j];
            ((__nv_bfloat162*)g_Wval_h)[j * 2]     = __floats2bfloat162_rn(v.x, v.y);
            ((__nv_bfloat162*)g_Wval_h)[j * 2 + 1] = __floats2bfloat162_rn(v.z, v.w);
        }
    }
}

// ---------------- tensor-core GEMM building blocks ----------------
__device__ __forceinline__ void ldsm4(uint32_t* r, const void* p) {
    uint32_t a = (uint32_t)__cvta_generic_to_shared(p);
    asm volatile("ldmatrix.sync.aligned.m8n8.x4.shared.b16 {%0,%1,%2,%3}, [%4];"
                 : "=r"(r[0]), "=r"(r[1]), "=r"(r[2]), "=r"(r[3]) : "r"(a));
}
__device__ __forceinline__ void ldsm4t(uint32_t* r, const void* p) {
    uint32_t a = (uint32_t)__cvta_generic_to_shared(p);
    asm volatile("ldmatrix.sync.aligned.m8n8.x4.trans.shared.b16 {%0,%1,%2,%3}, [%4];"
                 : "=r"(r[0]), "=r"(r[1]), "=r"(r[2]), "=r"(r[3]) : "r"(a));
}
__device__ __forceinline__ void mma_bf16(float* d, const uint32_t* a, const uint32_t* b) {
    asm volatile("mma.sync.aligned.m16n8k16.row.col.f32.bf16.bf16.f32 "
                 "{%0,%1,%2,%3}, {%4,%5,%6,%7}, {%8,%9}, {%0,%1,%2,%3};"
                 : "+f"(d[0]), "+f"(d[1]), "+f"(d[2]), "+f"(d[3])
                 : "r"(a[0]), "r"(a[1]), "r"(a[2]), "r"(a[3]), "r"(b[0]), "r"(b[1]));
}
__device__ __forceinline__ void cpa16(void* dst, const void* src) {
    uint32_t d = (uint32_t)__cvta_generic_to_shared(dst);
    asm volatile("cp.async.cg.shared.global [%0], [%1], 16;" :: "r"(d), "l"(src));
}
__device__ __forceinline__ void store2(float* C, float x, float y) {
    *(float2*)C = make_float2(x, y);
}
__device__ __forceinline__ void store2(__nv_bfloat16* C, float x, float y) {
    *(__nv_bfloat162*)C = __floats2bfloat162_rn(x, y);
}

// ================== bf16 cp.async GEMM (128x64 tile) ==================
#define STAGES 4
template<int EPI, typename OutT>
__global__ __launch_bounds__(256, 2) void hgemm_bf16(
    const __nv_bfloat16* __restrict__ A, const __nv_bfloat16* __restrict__ B,
    const float* __restrict__ bias, OutT* __restrict__ C,
    int M, int N, int K)
{
    __shared__ __align__(16) __nv_bfloat16 As[STAGES][128][40];
    __shared__ __align__(16) __nv_bfloat16 Bs[STAGES][32][72];   // [k][n]
    const int tid = threadIdx.x;
    const int bm = blockIdx.x * 128, bn = blockIdx.y * 64;
    const int lane = tid & 31, w = tid >> 5;
    const int m0 = (w >> 1) * 32, n0 = (w & 1) * 32;

    float acc[2][4][4];
    #pragma unroll
    for (int i = 0; i < 2; i++)
        #pragma unroll
        for (int j = 0; j < 4; j++)
            #pragma unroll
            for (int l = 0; l < 4; l++) acc[i][j][l] = 0.0f;

    const int arow = tid >> 1, acol = (tid & 1) * 16;
    const int brow = tid >> 3, bcol = (tid & 7) * 8;

    const __nv_bfloat16* Asrc = A + (size_t)(bm + arow) * K + acol;
    const __nv_bfloat16* Bsrc = B + bn + bcol;

    const int KT = K >> 5;

#define ISSUE(s, kt) do {                                                      \
    cpa16(&As[s][arow][acol],     Asrc + (kt) * 32);                           \
    cpa16(&As[s][arow][acol + 8], Asrc + (kt) * 32 + 8);                       \
    cpa16(&Bs[s][brow][bcol],     Bsrc + (size_t)((kt) * 32 + brow) * N);      \
} while (0)

#define COMPUTE_T(b) do {                                                      \
    _Pragma("unroll")                                                          \
    for (int ks = 0; ks < 2; ks++) {                                           \
        uint32_t af[2][4], bfr[4][2];                                          \
        _Pragma("unroll")                                                      \
        for (int mt = 0; mt < 2; mt++)                                         \
            ldsm4(af[mt], &As[b][m0 + mt * 16 + (lane & 15)]                   \
                             [ks * 16 + ((lane >> 4) << 3)]);                  \
        _Pragma("unroll")                                                      \
        for (int nt2 = 0; nt2 < 2; nt2++) {                                    \
            uint32_t t[4];                                                     \
            ldsm4t(t, &Bs[b][ks * 16 + (lane & 7) + 8 * ((lane >> 3) & 1)]     \
                            [n0 + nt2 * 16 + 8 * (lane >> 4)]);                \
            bfr[nt2 * 2][0] = t[0];      bfr[nt2 * 2][1] = t[1];               \
            bfr[nt2 * 2 + 1][0] = t[2];  bfr[nt2 * 2 + 1][1] = t[3];           \
        }                                                                      \
        _Pragma("unroll")                                                      \
        for (int mt = 0; mt < 2; mt++)                                         \
            _Pragma("unroll")                                                  \
            for (int nt = 0; nt < 4; nt++)                                     \
                mma_bf16(acc[mt][nt], af[mt], bfr[nt]);                        \
    }                                                                          \
} while (0)

    #pragma unroll
    for (int s = 0; s < STAGES - 1; s++) {
        if (s < KT) ISSUE(s, s);
        asm volatile("cp.async.commit_group;");
    }

    for (int kt = 0; kt < KT; kt++) {
        asm volatile("cp.async.wait_group %0;" :: "n"(STAGES - 2));
        __syncthreads();
        int kn = kt + STAGES - 1;
        if (kn < KT) ISSUE(kn & (STAGES - 1), kn);
        asm volatile("cp.async.commit_group;");
        COMPUTE_T(kt & (STAGES - 1));
    }
#undef ISSUE
#undef COMPUTE_T

    const int row0 = bm + m0 + (lane >> 2);
    #pragma unroll
    for (int mt = 0; mt < 2; mt++) {
        int r0 = row0 + mt * 16, r1 = r0 + 8;
        #pragma unroll
        for (int nt = 0; nt < 4; nt++) {
            int col = bn + n0 + nt * 8 + ((lane & 3) << 1);
            float b0 = 0.f, b1 = 0.f;
            if (EPI >= 1) { b0 = __ldg(bias + col); b1 = __ldg(bias + col + 1); }
            float v0 = acc[mt][nt][0] + b0, v1 = acc[mt][nt][1] + b1;
            float v2 = acc[mt][nt][2] + b0, v3 = acc[mt][nt][3] + b1;
            if (EPI == 2) {
                v0 = fmaxf(v0, 0.f); v1 = fmaxf(v1, 0.f);
                v2 = fmaxf(v2, 0.f); v3 = fmaxf(v3, 0.f);
            }
            store2(C + (size_t)r0 * N + col, v0, v1);
            store2(C + (size_t)r1 * N + col, v2, v3);
        }
    }
}

// ================== wide bf16 cp.async GEMM (128x128 tile; vproj) ==========
// C(MxN) = A*B + bias -> bf16. 8 warps as 4(m)x2(n), each 32x64.
// Halved B traffic, 32 mma per 12 ldsm. Requires N == gridDim.y*128.
__global__ __launch_bounds__(256, 2) void hgemm_wide(
    const __nv_bfloat16* __restrict__ A, const __nv_bfloat16* __restrict__ B,
    const float* __restrict__ bias, __nv_bfloat16* __restrict__ C,
    int M, int N, int K)
{
    __shared__ __align__(16) __nv_bfloat16 As[STAGES][128][40];
    __shared__ __align__(16) __nv_bfloat16 Bs[STAGES][32][136];  // [k][n], pad 136
    const int tid = threadIdx.x;
    const int bm = blockIdx.x * 128, bn = blockIdx.y * 128;
    const int lane = tid & 31, w = tid >> 5;
    const int m0 = (w & 3) * 32, n0 = (w >> 2) * 64;

    float acc[2][8][4];
    #pragma unroll
    for (int i = 0; i < 2; i++)
        #pragma unroll
        for (int j = 0; j < 8; j++)
            #pragma unroll
            for (int l = 0; l < 4; l++) acc[i][j][l] = 0.0f;

    const int arow = tid >> 1, acol = (tid & 1) * 16;
    const int brow = tid >> 3, bcol = (tid & 7) * 16;

    const __nv_bfloat16* Asrc = A + (size_t)(bm + arow) * K + acol;
    const __nv_bfloat16* Bsrc = B + bn + bcol;

    const int KT = K >> 5;

#define ISSUE_W(s, kt) do {                                                    \
    cpa16(&As[s][arow][acol],     Asrc + (kt) * 32);                           \
    cpa16(&As[s][arow][acol + 8], Asrc + (kt) * 32 + 8);                       \
    cpa16(&Bs[s][brow][bcol],     Bsrc + (size_t)((kt) * 32 + brow) * N);      \
    cpa16(&Bs[s][brow][bcol + 8], Bsrc + (size_t)((kt) * 32 + brow) * N + 8);  \
} while (0)

#define COMPUTE_W(b) do {                                                      \
    _Pragma("unroll")                                                          \
    for (int ks = 0; ks < 2; ks++) {                                           \
        uint32_t af[2][4], bfr[8][2];                                          \
        _Pragma("unroll")                                                      \
        for (int mt = 0; mt < 2; mt++)                                         \
            ldsm4(af[mt], &As[b][m0 + mt * 16 + (lane & 15)]                   \
                             [ks * 16 + ((lane >> 4) << 3)]);                  \
        _Pragma("unroll")                                                      \
        for (int nt2 = 0; nt2 < 4; nt2++) {                                    \
            uint32_t t[4];                                                     \
            ldsm4t(t, &Bs[b][ks * 16 + (lane & 7) + 8 * ((lane >> 3) & 1)]     \
                            [n0 + nt2 * 16 + 8 * (lane >> 4)]);                \
            bfr[nt2 * 2][0] = t[0];      bfr[nt2 * 2][1] = t[1];               \
            bfr[nt2 * 2 + 1][0] = t[2];  bfr[nt2 * 2 + 1][1] = t[3];           \
        }                                                                      \
        _Pragma("unroll")                                                      \
        for (int mt = 0; mt < 2; mt++)                                         \
            _Pragma("unroll")                                                  \
            for (int nt = 0; nt < 8; nt++)                                     \
                mma_bf16(acc[mt][nt], af[mt], bfr[nt]);                        \
    }                                                                          \
} while (0)

    #pragma unroll
    for (int s = 0; s < STAGES - 1; s++) {
        if (s < KT) ISSUE_W(s, s);
        asm volatile("cp.async.commit_group;");
    }

    for (int kt = 0; kt < KT; kt++) {
        asm volatile("cp.async.wait_group %0;" :: "n"(STAGES - 2));
        __syncthreads();
        int kn = kt + STAGES - 1;
        if (kn < KT) ISSUE_W(kn & (STAGES - 1), kn);
        asm volatile("cp.async.commit_group;");
        COMPUTE_W(kt & (STAGES - 1));
    }
#undef ISSUE_W
#undef COMPUTE_W

    const int row0 = bm + m0 + (lane >> 2);
    #pragma unroll
    for (int mt = 0; mt < 2; mt++) {
        int r0 = row0 + mt * 16, r1 = r0 + 8;
        #pragma unroll
        for (int nt = 0; nt < 8; nt++) {
            int col = bn + n0 + nt * 8 + ((lane & 3) << 1);
            float b0 = __ldg(bias + col), b1 = __ldg(bias + col + 1);
            store2(C + (size_t)r0 * N + col, acc[mt][nt][0] + b0, acc[mt][nt][1] + b1);
            store2(C + (size_t)r1 * N + col, acc[mt][nt][2] + b0, acc[mt][nt][3] + b1);
        }
    }
}

// ---------------- deformable sampling + cross-camera aggregation ----------------
// (R15 version: level-warp mapping + chained predicated corner dedup)
__global__ __launch_bounds__(256) void sample_kernel(
    const float* __restrict__ ref)   // (6, 6400, 4, 2)
{
    __shared__ float4 sw[768];
    __shared__ int4 sidx[768];
    __shared__ float saw[128];
    __shared__ float4 sred[256][2];
    const int n = blockIdx.x;
    const int tid = threadIdx.x;
    const unsigned int vism = g_vis[n];

    // Phase 0: softmax over each 16-point group (8 heads)
    if (tid < 128) {
        float lv = g_fused[(size_t)n * NFUS + 256 + tid];
        float mx = lv;
        #pragma unroll
        for (int o = 8; o > 0; o >>= 1)
            mx = fmaxf(mx, __shfl_xor_sync(0xffffffffu, mx, o));
        float e = expf(lv - mx);
        float s = e;
        #pragma unroll
        for (int o = 8; o > 0; o >>= 1)
            s += __shfl_xor_sync(0xffffffffu, s, o);
        saw[tid] = e / s;
    }
    __syncthreads();

    // Phase 1: weights + corner row indices
    #pragma unroll
    for (int t = 0; t < 3; t++) {
        int cid = tid + t * 256;
        int k = cid >> 7;
        int r = cid & 127;          // h*16 + lvl*4 + p
        int h = r >> 4;
        int lvl = (r >> 2) & 3;
        int p = r & 3;
        float4 wv = make_float4(0.f, 0.f, 0.f, 0.f);
        int4 iv = make_int4(0, 0, 0, 0);
        if ((vism >> k) & 1) {
            int Wi = c_W[lvl], Hi = c_H[lvl];
            float Wf = (float)Wi, Hf = (float)Hi;
            const float* rp = ref + (((size_t)k * NQ + n) * 4 + lvl) * 2;
            float rx = rp[0], ry = rp[1];
            int oi = ((h * 4 + lvl) * 4 + p) * 2;
            float ox = g_fused[(size_t)n * NFUS + oi];
            float oy = g_fused[(size_t)n * NFUS + oi + 1];
            float x = (rx + ox / Wf) * Wf - 0.5f;
            float y = (ry + oy / Hf) * Hf - 0.5f;
            float x0f = floorf(x), y0f = floorf(y);
            float lx = x - x0f, ly = y - y0f;
            int x0 = (int)x0f, y0 = (int)y0f;
            float a = saw[r];
            bool vx0 = (x0 >= 0) && (x0 < Wi);
            bool vx1 = (x0 + 1 >= 0) && (x0 + 1 < Wi);
            bool vy0 = (y0 >= 0) && (y0 < Hi);
            bool vy1 = (y0 + 1 >= 0) && (y0 + 1 < Hi);
            float omx = 1.0f - lx, omy = 1.0f - ly;
            wv.x = (vx0 && vy0) ? a * omx * omy : 0.0f;
            wv.y = (vx1 && vy0) ? a * lx * omy : 0.0f;
            wv.z = (vx0 && vy1) ? a * omx * ly : 0.0f;
            wv.w = (vx1 && vy1) ? a * lx * ly : 0.0f;
            int xc0 = min(max(x0, 0), Wi - 1);
            int xc1 = min(max(x0 + 1, 0), Wi - 1);
            int yc0 = min(max(y0, 0), Hi - 1);
            int yc1 = min(max(y0 + 1, 0), Hi - 1);
            int rb = k * LTOT + c_S[lvl];
            int r0 = rb + yc0 * Wi, r1 = rb + yc1 * Wi;
            iv = make_int4(r0 + xc0, r0 + xc1, r1 + xc0, r1 + xc1);
        }
        sw[cid] = wv;
        sidx[cid] = iv;
    }
    __syncthreads();

    // Phase 2: warp = (level, cam-triple); chain corner-reuse across points.
    const int cg = tid & 31;              // 8-channel group
    const int hh = cg >> 2;               // head
    const int w5 = tid >> 5;              // warp id 0..7
    const int lvl = w5 & 3;               // level handled by this warp
    const int kb = (w5 >> 2) * 3;         // cams {0,1,2} or {3,4,5}
    const __nv_bfloat16* vb = g_vproj + cg * 8;
    u64 a0 = 0, a1 = 0, a2 = 0, a3 = 0;

    #pragma unroll 1
    for (int c = 0; c < 3; c++) {
        const int k = kb + c;
        if (!((vism >> k) & 1)) continue;
        const int base = k * 128 + hh * 16 + lvl * 4;
        int4 ivp = make_int4(-1, -1, -1, -1);
        uint4 q0 = make_uint4(0, 0, 0, 0), q1 = q0, q2 = q0, q3 = q0;
        #pragma unroll
        for (int p = 0; p < 4; p++) {
            float4 w = sw[base + p];
            int4 iv = sidx[base + p];
            int diff = (iv.x ^ ivp.x) | (iv.y ^ ivp.y) |
                       (iv.z ^ ivp.z) | (iv.w ^ ivp.w);
            ldg128_pred(q0, vb + ((size_t)iv.x << 8), diff);
            ldg128_pred(q1, vb + ((size_t)iv.y << 8), diff);
            ldg128_pred(q2, vb + ((size_t)iv.z << 8), diff);
            ldg128_pred(q3, vb + ((size_t)iv.w << 8), diff);
            ivp = iv;
            u64 w0 = pkf2(w.x, w.x), w1 = pkf2(w.y, w.y);
            u64 w2 = pkf2(w.z, w.z), w3 = pkf2(w.w, w.w);
            ffma2(a0, w0, bf2f2(q0.x)); ffma2(a1, w0, bf2f2(q0.y));
            ffma2(a2, w0, bf2f2(q0.z)); ffma2(a3, w0, bf2f2(q0.w));
            ffma2(a0, w1, bf2f2(q1.x)); ffma2(a1, w1, bf2f2(q1.y));
            ffma2(a2, w1, bf2f2(q1.z)); ffma2(a3, w1, bf2f2(q1.w));
            ffma2(a0, w2, bf2f2(q2.x)); ffma2(a1, w2, bf2f2(q2.y));
            ffma2(a2, w2, bf2f2(q2.z)); ffma2(a3, w2, bf2f2(q2.w));
            ffma2(a0, w3, bf2f2(q3.x)); ffma2(a1, w3, bf2f2(q3.y));
            ffma2(a2, w3, bf2f2(q3.z)); ffma2(a3, w3, bf2f2(q3.w));
        }
    }

    float2 f0 = upk(a0), f1 = upk(a1), f2 = upk(a2), f3 = upk(a3);
    sred[tid][0] = make_float4(f0.x, f0.y, f1.x, f1.y);
    sred[tid][1] = make_float4(f2.x, f2.y, f3.x, f3.y);
    __syncthreads();
    if (tid < 128) {
        float4 x0 = sred[tid + 128][0], x1 = sred[tid + 128][1];
        float4 y0 = sred[tid][0], y1 = sred[tid][1];
        y0.x += x0.x; y0.y += x0.y; y0.z += x0.z; y0.w += x0.w;
        y1.x += x1.x; y1.y += x1.y; y1.z += x1.z; y1.w += x1.w;
        sred[tid][0] = y0; sred[tid][1] = y1;
    }
    __syncthreads();
    if (tid < 64) {
        float4 x0 = sred[tid + 64][0], x1 = sred[tid + 64][1];
        float4 y0 = sred[tid][0], y1 = sred[tid][1];
        y0.x += x0.x; y0.y += x0.y; y0.z += x0.z; y0.w += x0.w;
        y1.x += x1.x; y1.y += x1.y; y1.z += x1.z; y1.w += x1.w;
        sred[tid][0] = y0; sred[tid][1] = y1;
    }
    __syncthreads();
    if (tid < 32) {
        float4 x0 = sred[tid + 32][0], x1 = sred[tid + 32][1];
        float4 y0 = sred[tid][0], y1 = sred[tid][1];
        y0.x += x0.x; y0.y += x0.y; y0.z += x0.z; y0.w += x0.w;
        y1.x += x1.x; y1.y += x1.y; y1.z += x1.z; y1.w += x1.w;
        __nv_bfloat162 p0 = __floats2bfloat162_rn(y0.x, y0.y);
        __nv_bfloat162 p1 = __floats2bfloat162_rn(y0.z, y0.w);
        __nv_bfloat162 p2 = __floats2bfloat162_rn(y1.x, y1.y);
        __nv_bfloat162 p3 = __floats2bfloat162_rn(y1.z, y1.w);
        uint4 pk;
        pk.x = *(uint32_t*)&p0; pk.y = *(uint32_t*)&p1;
        pk.z = *(uint32_t*)&p2; pk.w = *(uint32_t*)&p3;
        *(uint4*)(g_aggh + (size_t)n * CH + tid * 8) = pk;
    }
}

// ---------------- block reduction helper ----------------
__device__ __forceinline__ float blocksum256(float v, float* sh) {
    #pragma unroll
    for (int o = 16; o > 0; o >>= 1) v += __shfl_xor_sync(0xffffffffu, v, o);
    if ((threadIdx.x & 31) == 0) sh[threadIdx.x >> 5] = v;
    __syncthreads();
    float s = 0.f;
    #pragma unroll
    for (int i = 0; i < 8; i++) s += sh[i];
    __syncthreads();
    return s;
}

// ---------------- slots assembly + residual + LN1 ----------------
__global__ __launch_bounds__(256) void ln1_kernel(
    const float* __restrict__ query, const float* __restrict__ b_out,
    const float* __restrict__ gamma, const float* __restrict__ beta)
{
    __shared__ float sh[8];
    const int n = blockIdx.x, c = threadIdx.x;
    float m = g_cnt[n];
    float q = query[(size_t)n * CH + c];
    float s = m * (q + b_out[c]) + g_proj[(size_t)n * CH + c];
    float t = s / fmaxf(m, 1.0f) + q;
    float mu = blocksum256(t, sh) * (1.0f / CH);
    float d = t - mu;
    float var = blocksum256(d * d, sh) * (1.0f / CH);
    float xv = d * rsqrtf(var + 1e-5f) * gamma[c] + beta[c];
    g_x[(size_t)n * CH + c] = xv;
    g_x_h[(size_t)n * CH + c] = __float2bfloat16_rn(xv);
}

// ---------------- FFN residual + LN2 -> output ----------------
__global__ __launch_bounds__(256) void ln2_kernel(
    const float* __restrict__ gamma, const float* __restrict__ beta,
    float* __restrict__ out)
{
    __shared__ float sh[8];
    const int n = blockIdx.x, c = threadIdx.x;
    float t = g_x[(size_t)n * CH + c] + g_ffn2[(size_t)n * CH + c];
    float mu = blocksum256(t, sh) * (1.0f / CH);
    float d = t - mu;
    float var = blocksum256(d * d, sh) * (1.0f / CH);
    out[(size_t)n * CH + c] = d * rsqrtf(var + 1e-5f) * gamma[c] + beta[c];
}

// ---------------- host launcher ----------------
extern "C" void kernel_launch(void* const* d_in, const int* in_sizes, int n_in,
                              void* d_out, int out_size) {
    const float* query   = (const float*)d_in[0];
    const float* value   = (const float*)d_in[2];
    const float* refpts  = (const float*)d_in[3];
    const int*   bev     = (const int*)d_in[6];
    const float* W_value = (const float*)d_in[7];
    const float* b_value = (const float*)d_in[8];
    const float* W_off   = (const float*)d_in[9];
    const float* b_off   = (const float*)d_in[10];
    const float* W_attn  = (const float*)d_in[11];
    const float* b_attn  = (const float*)d_in[12];
    const float* W_out   = (const float*)d_in[13];
    const float* b_out   = (const float*)d_in[14];
    const float* ln1_g   = (const float*)d_in[15];
    const float* ln1_b   = (const float*)d_in[16];
    const float* W1      = (const float*)d_in[17];
    const float* b1      = (const float*)d_in[18];
    const float* W2      = (const float*)d_in[19];
    const float* b2      = (const float*)d_in[20];
    const float* ln2_g   = (const float*)d_in[21];
    const float* ln2_b   = (const float*)d_in[22];
    float* out = (float*)d_out;

    void *p_valh, *p_Wvalh, *p_vproj, *p_qh, *p_Wfh, *p_bf, *p_Wouth, *p_W1h, *p_W2h;
    void *p_fused, *p_aggh, *p_proj, *p_xh, *p_ffn1h, *p_ffn2;
    cudaGetSymbolAddress(&p_valh,   g_val_h);
    cudaGetSymbolAddress(&p_Wvalh,  g_Wval_h);
    cudaGetSymbolAddress(&p_vproj,  g_vproj);
    cudaGetSymbolAddress(&p_qh,     g_q_h);
    cudaGetSymbolAddress(&p_Wfh,    g_Wf_h);
    cudaGetSymbolAddress(&p_bf,     g_bf);
    cudaGetSymbolAddress(&p_Wouth,  g_Wout_h);
    cudaGetSymbolAddress(&p_W1h,    g_W1_h);
    cudaGetSymbolAddress(&p_W2h,    g_W2_h);
    cudaGetSymbolAddress(&p_fused,  g_fused);
    cudaGetSymbolAddress(&p_aggh,   g_aggh);
    cudaGetSymbolAddress(&p_proj,   g_proj);
    cudaGetSymbolAddress(&p_xh,     g_x_h);
    cudaGetSymbolAddress(&p_ffn1h,  g_ffn1h);
    cudaGetSymbolAddress(&p_ffn2,   g_ffn2);

    static cudaStream_t s2 = nullptr;
    static cudaEvent_t ev_fork = nullptr, ev_join = nullptr;
    if (s2 == nullptr) {
        cudaStreamCreateWithFlags(&s2, cudaStreamNonBlocking);
        cudaEventCreateWithFlags(&ev_fork, cudaEventDisableTiming);
        cudaEventCreateWithFlags(&ev_join, cudaEventDisableTiming);
    }

    // ---- fork: value/W_value conversion + wide vproj GEMM (bf16 out) on s2 ----
    cudaEventRecord(ev_fork, 0);
    cudaStreamWaitEvent(s2, ev_fork, 0);
    {
        int nconv = (MVAL * CH / 4 + CH * CH / 4 + 255) / 256;
        conv_val_kernel<<<nconv, 256, 0, s2>>>(value, W_value);
        hgemm_wide<<<dim3(MPAD / 128, CH / 128), 256, 0, s2>>>(
            (const __nv_bfloat16*)p_valh, (const __nv_bfloat16*)p_Wvalh,
            b_value, (__nv_bfloat16*)p_vproj, MPAD, CH, CH);
    }
    cudaEventRecord(ev_join, s2);

    // ---- main stream: prep + fused off/attn GEMM ----
    prep_kernel<<<2585, 256>>>(bev, query, W_off, W_attn, b_off, b_attn,
                               W_out, W1, W2);
    hgemm_bf16<1, float><<<dim3(NQ / 128, NFUS / 64), 256>>>(
        (const __nv_bfloat16*)p_qh, (const __nv_bfloat16*)p_Wfh,
        (const float*)p_bf, (float*)p_fused, NQ, NFUS, CH);

    // ---- join, then sampling ----
    cudaStreamWaitEvent(0, ev_join, 0);
    sample_kernel<<<NQ, 256>>>(refpts);

    // output projection: agg(bf16) @ W_out (bias folded into ln1)
    hgemm_bf16<0, float><<<dim3(NQ / 128, CH / 64), 256>>>(
        (const __nv_bfloat16*)p_aggh, (const __nv_bfloat16*)p_Wouth,
        nullptr, (float*)p_proj, NQ, CH, CH);

    // slots + residual + LN1
    ln1_kernel<<<NQ, 256>>>(query, b_out, ln1_g, ln1_b);

    // FFN up: relu(x @ W1 + b1) -> bf16
    hgemm_bf16<2, __nv_bfloat16><<<dim3(NQ / 128, DFFN / 64), 256>>>(
        (const __nv_bfloat16*)p_xh, (const __nv_bfloat16*)p_W1h,
        b1, (__nv_bfloat16*)p_ffn1h, NQ, DFFN, CH);

    // FFN down: ffn1(bf16) @ W2 + b2
    hgemm_bf16<1, float><<<dim3(NQ / 128, CH / 64), 256>>>(
        (const __nv_bfloat16*)p_ffn1h, (const __nv_bfloat16*)p_W2h,
        b2, (float*)p_ffn2, NQ, CH, DFFN);

    // residual + LN2 -> out
    ln2_kernel<<<NQ, 256>>>(ln2_g, ln2_b, out);

    (void)in_sizes; (void)n_in; (void)out_size;
}

// round 17
// speedup vs baseline: 1.1688x; 1.0117x over previous
#include <cuda_runtime.h>
#include <cuda_bf16.h>
#include <stdint.h>

// Problem constants (fixed by setup_inputs)
#define NQ   6400
#define CAMS 6
#define LTOT 7979
#define CH   256
#define DFFN 1024
#define NFUS 384   // fused off(256) + attn-logits(128)
#define MVAL (CAMS * LTOT)   // 47874
#define MPAD 48000           // 375 * 128

typedef unsigned long long u64;

// ---------------- scratch (static device globals; no allocation) ----------------
__device__ __nv_bfloat16 g_val_h[MPAD * CH];        // value in bf16 (padded rows stay 0)
__device__ __nv_bfloat16 g_Wval_h[CH * CH];         // W_value bf16
__device__ __nv_bfloat16 g_vproj[MPAD * CH];        // value @ W_value + b (bf16)
__device__ __nv_bfloat16 g_q_h[NQ * CH];            // query in bf16
__device__ __nv_bfloat16 g_Wf_h[CH * NFUS];         // fused [W_off | W_attn] bf16
__device__ float g_bf[NFUS];                        // fused bias (fp32)
__device__ __nv_bfloat16 g_Wout_h[CH * CH];         // W_out bf16
__device__ __nv_bfloat16 g_W1_h[CH * DFFN];         // W1 bf16
__device__ __nv_bfloat16 g_W2_h[DFFN * CH];         // W2 bf16
__device__ float g_fused[NQ * NFUS];                // fused offsets + attn logits
__device__ __nv_bfloat16 g_aggh[NQ * CH];           // aggregated samples (bf16)
__device__ float g_proj[NQ * CH];                   // agg @ W_out
__device__ float g_x[NQ * CH];                      // after LN1 (fp32)
__device__ __nv_bfloat16 g_x_h[NQ * CH];            // after LN1 (bf16)
__device__ __nv_bfloat16 g_ffn1h[NQ * DFFN];        // relu(x@W1+b1) (bf16)
__device__ float g_ffn2[NQ * CH];                   // ffn1@W2+b2
__device__ unsigned int g_vis[NQ];                  // camera visibility bitmask
__device__ float g_cnt[NQ];                         // number of visible cameras

__constant__ int c_W[4] = {100, 50, 25, 13};
__constant__ int c_H[4] = {60, 30, 15, 8};
__constant__ int c_S[4] = {0, 6000, 7500, 7875};

// ---------------- f32x2 packed-math helpers ----------------
__device__ __forceinline__ u64 pkf2(float lo, float hi) {
    u64 r; asm("mov.b64 %0, {%1, %2};" : "=l"(r) : "f"(lo), "f"(hi)); return r;
}
__device__ __forceinline__ u64 bf2f2(uint32_t v) {
    uint32_t lo = v << 16, hi = v & 0xFFFF0000u;
    u64 r; asm("mov.b64 %0, {%1, %2};" : "=l"(r) : "r"(lo), "r"(hi)); return r;
}
__device__ __forceinline__ void ffma2(u64& d, u64 a, u64 b) {
    asm("fma.rn.f32x2 %0, %1, %2, %0;" : "+l"(d) : "l"(a), "l"(b));
}
__device__ __forceinline__ float2 upk(u64 v) {
    float2 f; asm("mov.b64 {%0, %1}, %2;" : "=f"(f.x), "=f"(f.y) : "l"(v)); return f;
}
// Predicated 16B global load (uniform predicate per warp here): only executes
// when doit != 0, else q keeps previous contents.
__device__ __forceinline__ void ldg128_pred(uint4& q, const __nv_bfloat16* p, int doit) {
    asm volatile("{\n\t"
        ".reg .pred pp;\n\t"
        "setp.ne.s32 pp, %5, 0;\n\t"
        "@pp ld.global.nc.v4.u32 {%0,%1,%2,%3}, [%4];\n\t"
        "}"
        : "+r"(q.x), "+r"(q.y), "+r"(q.z), "+r"(q.w)
        : "l"(p), "r"(doit));
}

// ---------------- fused prep: mask + query/weight fp32->bf16 ----------------
__global__ __launch_bounds__(256) void prep_kernel(
    const int* __restrict__ bev, const float* __restrict__ query,
    const float* __restrict__ Woff, const float* __restrict__ Wattn,
    const float* __restrict__ boff, const float* __restrict__ battn,
    const float* __restrict__ Wout, const float* __restrict__ W1,
    const float* __restrict__ W2)
{
    const int b = blockIdx.x, tid = threadIdx.x;
    if (b < 25) {
        int n = b * 256 + tid;
        unsigned int vm = 0; int cnt = 0;
        #pragma unroll
        for (int k = 0; k < CAMS; k++) {
            const int* bp = bev + ((size_t)k * NQ + n) * 4;
            if (bp[0] + bp[1] + bp[2] + bp[3] > 0) { vm |= (1u << k); cnt++; }
        }
        g_vis[n] = vm;
        g_cnt[n] = (float)cnt;
    } else if (b < 1625) {
        int i = (b - 25) * 256 + tid;           // float4 index, < 409600
        float4 v = ((const float4*)query)[i];
        ((__nv_bfloat162*)g_q_h)[i * 2]     = __floats2bfloat162_rn(v.x, v.y);
        ((__nv_bfloat162*)g_q_h)[i * 2 + 1] = __floats2bfloat162_rn(v.z, v.w);
    } else if (b < 2009) {
        int i = (b - 1625) * 256 + tid;         // < 98304
        int k = i / NFUS, n = i % NFUS;
        float v = (n < 256) ? Woff[k * 256 + n] : Wattn[k * 128 + (n - 256)];
        g_Wf_h[i] = __float2bfloat16_rn(v);
        if (i < NFUS) g_bf[i] = (i < 256) ? boff[i] : battn[i - 256];
    } else if (b < 2073) {
        int i = (b - 2009) * 256 + tid;         // < 16384
        float4 v = ((const float4*)Wout)[i];
        ((__nv_bfloat162*)g_Wout_h)[i * 2]     = __floats2bfloat162_rn(v.x, v.y);
        ((__nv_bfloat162*)g_Wout_h)[i * 2 + 1] = __floats2bfloat162_rn(v.z, v.w);
    } else if (b < 2329) {
        int i = (b - 2073) * 256 + tid;         // < 65536
        float4 v = ((const float4*)W1)[i];
        ((__nv_bfloat162*)g_W1_h)[i * 2]     = __floats2bfloat162_rn(v.x, v.y);
        ((__nv_bfloat162*)g_W1_h)[i * 2 + 1] = __floats2bfloat162_rn(v.z, v.w);
    } else {
        int i = (b - 2329) * 256 + tid;         // < 65536
        float4 v = ((const float4*)W2)[i];
        ((__nv_bfloat162*)g_W2_h)[i * 2]     = __floats2bfloat162_rn(v.x, v.y);
        ((__nv_bfloat162*)g_W2_h)[i * 2 + 1] = __floats2bfloat162_rn(v.z, v.w);
    }
}

// ---------------- value + W_value fp32 -> bf16 (stream 2) ----------------
__global__ __launch_bounds__(256) void conv_val_kernel(
    const float* __restrict__ val, const float* __restrict__ Wv)
{
    const int NV = MVAL * CH / 4;   // 3,063,936
    int i = blockIdx.x * 256 + threadIdx.x;
    if (i < NV) {
        float4 v = ((const float4*)val)[i];
        ((__nv_bfloat162*)g_val_h)[i * 2]     = __floats2bfloat162_rn(v.x, v.y);
        ((__nv_bfloat162*)g_val_h)[i * 2 + 1] = __floats2bfloat162_rn(v.z, v.w);
    } else {
        int j = i - NV;
        if (j < CH * CH / 4) {
            float4 v = ((const float4*)Wv)[j];
            ((__nv_bfloat162*)g_Wval_h)[j * 2]     = __floats2bfloat162_rn(v.x, v.y);
            ((__nv_bfloat162*)g_Wval_h)[j * 2 + 1] = __floats2bfloat162_rn(v.z, v.w);
        }
    }
}

// ---------------- tensor-core GEMM building blocks ----------------
__device__ __forceinline__ void ldsm4(uint32_t* r, const void* p) {
    uint32_t a = (uint32_t)__cvta_generic_to_shared(p);
    asm volatile("ldmatrix.sync.aligned.m8n8.x4.shared.b16 {%0,%1,%2,%3}, [%4];"
                 : "=r"(r[0]), "=r"(r[1]), "=r"(r[2]), "=r"(r[3]) : "r"(a));
}
__device__ __forceinline__ void ldsm4t(uint32_t* r, const void* p) {
    uint32_t a = (uint32_t)__cvta_generic_to_shared(p);
    asm volatile("ldmatrix.sync.aligned.m8n8.x4.trans.shared.b16 {%0,%1,%2,%3}, [%4];"
                 : "=r"(r[0]), "=r"(r[1]), "=r"(r[2]), "=r"(r[3]) : "r"(a));
}
__device__ __forceinline__ void mma_bf16(float* d, const uint32_t* a, const uint32_t* b) {
    asm volatile("mma.sync.aligned.m16n8k16.row.col.f32.bf16.bf16.f32 "
                 "{%0,%1,%2,%3}, {%4,%5,%6,%7}, {%8,%9}, {%0,%1,%2,%3};"
                 : "+f"(d[0]), "+f"(d[1]), "+f"(d[2]), "+f"(d[3])
                 : "r"(a[0]), "r"(a[1]), "r"(a[2]), "r"(a[3]), "r"(b[0]), "r"(b[1]));
}
__device__ __forceinline__ void cpa16(void* dst, const void* src) {
    uint32_t d = (uint32_t)__cvta_generic_to_shared(dst);
    asm volatile("cp.async.cg.shared.global [%0], [%1], 16;" :: "r"(d), "l"(src));
}
__device__ __forceinline__ void store2(float* C, float x, float y) {
    *(float2*)C = make_float2(x, y);
}
__device__ __forceinline__ void store2(__nv_bfloat16* C, float x, float y) {
    *(__nv_bfloat162*)C = __floats2bfloat162_rn(x, y);
}

// ================== bf16 cp.async GEMM (128x64 tile) ==================
#define STAGES 4
template<int EPI, typename OutT>
__global__ __launch_bounds__(256, 2) void hgemm_bf16(
    const __nv_bfloat16* __restrict__ A, const __nv_bfloat16* __restrict__ B,
    const float* __restrict__ bias, OutT* __restrict__ C,
    int M, int N, int K)
{
    __shared__ __align__(16) __nv_bfloat16 As[STAGES][128][40];
    __shared__ __align__(16) __nv_bfloat16 Bs[STAGES][32][72];   // [k][n]
    const int tid = threadIdx.x;
    const int bm = blockIdx.x * 128, bn = blockIdx.y * 64;
    const int lane = tid & 31, w = tid >> 5;
    const int m0 = (w >> 1) * 32, n0 = (w & 1) * 32;

    float acc[2][4][4];
    #pragma unroll
    for (int i = 0; i < 2; i++)
        #pragma unroll
        for (int j = 0; j < 4; j++)
            #pragma unroll
            for (int l = 0; l < 4; l++) acc[i][j][l] = 0.0f;

    const int arow = tid >> 1, acol = (tid & 1) * 16;
    const int brow = tid >> 3, bcol = (tid & 7) * 8;

    const __nv_bfloat16* Asrc = A + (size_t)(bm + arow) * K + acol;
    const __nv_bfloat16* Bsrc = B + bn + bcol;

    const int KT = K >> 5;

#define ISSUE(s, kt) do {                                                      \
    cpa16(&As[s][arow][acol],     Asrc + (kt) * 32);                           \
    cpa16(&As[s][arow][acol + 8], Asrc + (kt) * 32 + 8);                       \
    cpa16(&Bs[s][brow][bcol],     Bsrc + (size_t)((kt) * 32 + brow) * N);      \
} while (0)

#define COMPUTE_T(b) do {                                                      \
    _Pragma("unroll")                                                          \
    for (int ks = 0; ks < 2; ks++) {                                           \
        uint32_t af[2][4], bfr[4][2];                                          \
        _Pragma("unroll")                                                      \
        for (int mt = 0; mt < 2; mt++)                                         \
            ldsm4(af[mt], &As[b][m0 + mt * 16 + (lane & 15)]                   \
                             [ks * 16 + ((lane >> 4) << 3)]);                  \
        _Pragma("unroll")                                                      \
        for (int nt2 = 0; nt2 < 2; nt2++) {                                    \
            uint32_t t[4];                                                     \
            ldsm4t(t, &Bs[b][ks * 16 + (lane & 7) + 8 * ((lane >> 3) & 1)]     \
                            [n0 + nt2 * 16 + 8 * (lane >> 4)]);                \
            bfr[nt2 * 2][0] = t[0];      bfr[nt2 * 2][1] = t[1];               \
            bfr[nt2 * 2 + 1][0] = t[2];  bfr[nt2 * 2 + 1][1] = t[3];           \
        }                                                                      \
        _Pragma("unroll")                                                      \
        for (int mt = 0; mt < 2; mt++)                                         \
            _Pragma("unroll")                                                  \
            for (int nt = 0; nt < 4; nt++)                                     \
                mma_bf16(acc[mt][nt], af[mt], bfr[nt]);                        \
    }                                                                          \
} while (0)

    #pragma unroll
    for (int s = 0; s < STAGES - 1; s++) {
        if (s < KT) ISSUE(s, s);
        asm volatile("cp.async.commit_group;");
    }

    for (int kt = 0; kt < KT; kt++) {
        asm volatile("cp.async.wait_group %0;" :: "n"(STAGES - 2));
        __syncthreads();
        int kn = kt + STAGES - 1;
        if (kn < KT) ISSUE(kn & (STAGES - 1), kn);
        asm volatile("cp.async.commit_group;");
        COMPUTE_T(kt & (STAGES - 1));
    }
#undef ISSUE
#undef COMPUTE_T

    const int row0 = bm + m0 + (lane >> 2);
    #pragma unroll
    for (int mt = 0; mt < 2; mt++) {
        int r0 = row0 + mt * 16, r1 = r0 + 8;
        #pragma unroll
        for (int nt = 0; nt < 4; nt++) {
            int col = bn + n0 + nt * 8 + ((lane & 3) << 1);
            float b0 = 0.f, b1 = 0.f;
            if (EPI >= 1) { b0 = __ldg(bias + col); b1 = __ldg(bias + col + 1); }
            float v0 = acc[mt][nt][0] + b0, v1 = acc[mt][nt][1] + b1;
            float v2 = acc[mt][nt][2] + b0, v3 = acc[mt][nt][3] + b1;
            if (EPI == 2) {
                v0 = fmaxf(v0, 0.f); v1 = fmaxf(v1, 0.f);
                v2 = fmaxf(v2, 0.f); v3 = fmaxf(v3, 0.f);
            }
            store2(C + (size_t)r0 * N + col, v0, v1);
            store2(C + (size_t)r1 * N + col, v2, v3);
        }
    }
}

// ================== wide bf16 cp.async GEMM (128x128 tile) ==================
// C(MxN) = A*B (+bias)(+relu). 8 warps as 4(m)x2(n), each 32x64. Halved B
// traffic, 32 mma per 12 ldsm. Requires M%128==0, N%128==0, K%32==0.
// EPI: 1 +bias, 2 +bias+relu.
template<int EPI, typename OutT>
__global__ __launch_bounds__(256, 2) void hgemm_wide(
    const __nv_bfloat16* __restrict__ A, const __nv_bfloat16* __restrict__ B,
    const float* __restrict__ bias, OutT* __restrict__ C,
    int M, int N, int K)
{
    __shared__ __align__(16) __nv_bfloat16 As[STAGES][128][40];
    __shared__ __align__(16) __nv_bfloat16 Bs[STAGES][32][136];  // [k][n], pad 136
    const int tid = threadIdx.x;
    const int bm = blockIdx.x * 128, bn = blockIdx.y * 128;
    const int lane = tid & 31, w = tid >> 5;
    const int m0 = (w & 3) * 32, n0 = (w >> 2) * 64;

    float acc[2][8][4];
    #pragma unroll
    for (int i = 0; i < 2; i++)
        #pragma unroll
        for (int j = 0; j < 8; j++)
            #pragma unroll
            for (int l = 0; l < 4; l++) acc[i][j][l] = 0.0f;

    const int arow = tid >> 1, acol = (tid & 1) * 16;
    const int brow = tid >> 3, bcol = (tid & 7) * 16;

    const __nv_bfloat16* Asrc = A + (size_t)(bm + arow) * K + acol;
    const __nv_bfloat16* Bsrc = B + bn + bcol;

    const int KT = K >> 5;

#define ISSUE_W(s, kt) do {                                                    \
    cpa16(&As[s][arow][acol],     Asrc + (kt) * 32);                           \
    cpa16(&As[s][arow][acol + 8], Asrc + (kt) * 32 + 8);                       \
    cpa16(&Bs[s][brow][bcol],     Bsrc + (size_t)((kt) * 32 + brow) * N);      \
    cpa16(&Bs[s][brow][bcol + 8], Bsrc + (size_t)((kt) * 32 + brow) * N + 8);  \
} while (0)

#define COMPUTE_W(b) do {                                                      \
    _Pragma("unroll")                                                          \
    for (int ks = 0; ks < 2; ks++) {                                           \
        uint32_t af[2][4], bfr[8][2];                                          \
        _Pragma("unroll")                                                      \
        for (int mt = 0; mt < 2; mt++)                                         \
            ldsm4(af[mt], &As[b][m0 + mt * 16 + (lane & 15)]                   \
                             [ks * 16 + ((lane >> 4) << 3)]);                  \
        _Pragma("unroll")                                                      \
        for (int nt2 = 0; nt2 < 4; nt2++) {                                    \
            uint32_t t[4];                                                     \
            ldsm4t(t, &Bs[b][ks * 16 + (lane & 7) + 8 * ((lane >> 3) & 1)]     \
                            [n0 + nt2 * 16 + 8 * (lane >> 4)]);                \
            bfr[nt2 * 2][0] = t[0];      bfr[nt2 * 2][1] = t[1];               \
            bfr[nt2 * 2 + 1][0] = t[2];  bfr[nt2 * 2 + 1][1] = t[3];           \
        }                                                                      \
        _Pragma("unroll")                                                      \
        for (int mt = 0; mt < 2; mt++)                                         \
            _Pragma("unroll")                                                  \
            for (int nt = 0; nt < 8; nt++)                                     \
                mma_bf16(acc[mt][nt], af[mt], bfr[nt]);                        \
    }                                                                          \
} while (0)

    #pragma unroll
    for (int s = 0; s < STAGES - 1; s++) {
        if (s < KT) ISSUE_W(s, s);
        asm volatile("cp.async.commit_group;");
    }

    for (int kt = 0; kt < KT; kt++) {
        asm volatile("cp.async.wait_group %0;" :: "n"(STAGES - 2));
        __syncthreads();
        int kn = kt + STAGES - 1;
        if (kn < KT) ISSUE_W(kn & (STAGES - 1), kn);
        asm volatile("cp.async.commit_group;");
        COMPUTE_W(kt & (STAGES - 1));
    }
#undef ISSUE_W
#undef COMPUTE_W

    const int row0 = bm + m0 + (lane >> 2);
    #pragma unroll
    for (int mt = 0; mt < 2; mt++) {
        int r0 = row0 + mt * 16, r1 = r0 + 8;
        #pragma unroll
        for (int nt = 0; nt < 8; nt++) {
            int col = bn + n0 + nt * 8 + ((lane & 3) << 1);
            float b0 = __ldg(bias + col), b1 = __ldg(bias + col + 1);
            float v0 = acc[mt][nt][0] + b0, v1 = acc[mt][nt][1] + b1;
            float v2 = acc[mt][nt][2] + b0, v3 = acc[mt][nt][3] + b1;
            if (EPI == 2) {
                v0 = fmaxf(v0, 0.f); v1 = fmaxf(v1, 0.f);
                v2 = fmaxf(v2, 0.f); v3 = fmaxf(v3, 0.f);
            }
            store2(C + (size_t)r0 * N + col, v0, v1);
            store2(C + (size_t)r1 * N + col, v2, v3);
        }
    }
}

// ---------------- deformable sampling + cross-camera aggregation ----------------
// (R15 version: level-warp mapping + chained predicated corner dedup)
__global__ __launch_bounds__(256) void sample_kernel(
    const float* __restrict__ ref)   // (6, 6400, 4, 2)
{
    __shared__ float4 sw[768];
    __shared__ int4 sidx[768];
    __shared__ float saw[128];
    __shared__ float4 sred[256][2];
    const int n = blockIdx.x;
    const int tid = threadIdx.x;
    const unsigned int vism = g_vis[n];

    // Phase 0: softmax over each 16-point group (8 heads)
    if (tid < 128) {
        float lv = g_fused[(size_t)n * NFUS + 256 + tid];
        float mx = lv;
        #pragma unroll
        for (int o = 8; o > 0; o >>= 1)
            mx = fmaxf(mx, __shfl_xor_sync(0xffffffffu, mx, o));
        float e = expf(lv - mx);
        float s = e;
        #pragma unroll
        for (int o = 8; o > 0; o >>= 1)
            s += __shfl_xor_sync(0xffffffffu, s, o);
        saw[tid] = e / s;
    }
    __syncthreads();

    // Phase 1: weights + corner row indices
    #pragma unroll
    for (int t = 0; t < 3; t++) {
        int cid = tid + t * 256;
        int k = cid >> 7;
        int r = cid & 127;          // h*16 + lvl*4 + p
        int h = r >> 4;
        int lvl = (r >> 2) & 3;
        int p = r & 3;
        float4 wv = make_float4(0.f, 0.f, 0.f, 0.f);
        int4 iv = make_int4(0, 0, 0, 0);
        if ((vism >> k) & 1) {
            int Wi = c_W[lvl], Hi = c_H[lvl];
            float Wf = (float)Wi, Hf = (float)Hi;
            const float* rp = ref + (((size_t)k * NQ + n) * 4 + lvl) * 2;
            float rx = rp[0], ry = rp[1];
            int oi = ((h * 4 + lvl) * 4 + p) * 2;
            float ox = g_fused[(size_t)n * NFUS + oi];
            float oy = g_fused[(size_t)n * NFUS + oi + 1];
            float x = (rx + ox / Wf) * Wf - 0.5f;
            float y = (ry + oy / Hf) * Hf - 0.5f;
            float x0f = floorf(x), y0f = floorf(y);
            float lx = x - x0f, ly = y - y0f;
            int x0 = (int)x0f, y0 = (int)y0f;
            float a = saw[r];
            bool vx0 = (x0 >= 0) && (x0 < Wi);
            bool vx1 = (x0 + 1 >= 0) && (x0 + 1 < Wi);
            bool vy0 = (y0 >= 0) && (y0 < Hi);
            bool vy1 = (y0 + 1 >= 0) && (y0 + 1 < Hi);
            float omx = 1.0f - lx, omy = 1.0f - ly;
            wv.x = (vx0 && vy0) ? a * omx * omy : 0.0f;
            wv.y = (vx1 && vy0) ? a * lx * omy : 0.0f;
            wv.z = (vx0 && vy1) ? a * omx * ly : 0.0f;
            wv.w = (vx1 && vy1) ? a * lx * ly : 0.0f;
            int xc0 = min(max(x0, 0), Wi - 1);
            int xc1 = min(max(x0 + 1, 0), Wi - 1);
            int yc0 = min(max(y0, 0), Hi - 1);
            int yc1 = min(max(y0 + 1, 0), Hi - 1);
            int rb = k * LTOT + c_S[lvl];
            int r0 = rb + yc0 * Wi, r1 = rb + yc1 * Wi;
            iv = make_int4(r0 + xc0, r0 + xc1, r1 + xc0, r1 + xc1);
        }
        sw[cid] = wv;
        sidx[cid] = iv;
    }
    __syncthreads();

    // Phase 2: warp = (level, cam-triple); chain corner-reuse across points.
    const int cg = tid & 31;              // 8-channel group
    const int hh = cg >> 2;               // head
    const int w5 = tid >> 5;              // warp id 0..7
    const int lvl = w5 & 3;               // level handled by this warp
    const int kb = (w5 >> 2) * 3;         // cams {0,1,2} or {3,4,5}
    const __nv_bfloat16* vb = g_vproj + cg * 8;
    u64 a0 = 0, a1 = 0, a2 = 0, a3 = 0;

    #pragma unroll 1
    for (int c = 0; c < 3; c++) {
        const int k = kb + c;
        if (!((vism >> k) & 1)) continue;
        const int base = k * 128 + hh * 16 + lvl * 4;
        int4 ivp = make_int4(-1, -1, -1, -1);
        uint4 q0 = make_uint4(0, 0, 0, 0), q1 = q0, q2 = q0, q3 = q0;
        #pragma unroll
        for (int p = 0; p < 4; p++) {
            float4 w = sw[base + p];
            int4 iv = sidx[base + p];
            int diff = (iv.x ^ ivp.x) | (iv.y ^ ivp.y) |
                       (iv.z ^ ivp.z) | (iv.w ^ ivp.w);
            ldg128_pred(q0, vb + ((size_t)iv.x << 8), diff);
            ldg128_pred(q1, vb + ((size_t)iv.y << 8), diff);
            ldg128_pred(q2, vb + ((size_t)iv.z << 8), diff);
            ldg128_pred(q3, vb + ((size_t)iv.w << 8), diff);
            ivp = iv;
            u64 w0 = pkf2(w.x, w.x), w1 = pkf2(w.y, w.y);
            u64 w2 = pkf2(w.z, w.z), w3 = pkf2(w.w, w.w);
            ffma2(a0, w0, bf2f2(q0.x)); ffma2(a1, w0, bf2f2(q0.y));
            ffma2(a2, w0, bf2f2(q0.z)); ffma2(a3, w0, bf2f2(q0.w));
            ffma2(a0, w1, bf2f2(q1.x)); ffma2(a1, w1, bf2f2(q1.y));
            ffma2(a2, w1, bf2f2(q1.z)); ffma2(a3, w1, bf2f2(q1.w));
            ffma2(a0, w2, bf2f2(q2.x)); ffma2(a1, w2, bf2f2(q2.y));
            ffma2(a2, w2, bf2f2(q2.z)); ffma2(a3, w2, bf2f2(q2.w));
            ffma2(a0, w3, bf2f2(q3.x)); ffma2(a1, w3, bf2f2(q3.y));
            ffma2(a2, w3, bf2f2(q3.z)); ffma2(a3, w3, bf2f2(q3.w));
        }
    }

    float2 f0 = upk(a0), f1 = upk(a1), f2 = upk(a2), f3 = upk(a3);
    sred[tid][0] = make_float4(f0.x, f0.y, f1.x, f1.y);
    sred[tid][1] = make_float4(f2.x, f2.y, f3.x, f3.y);
    __syncthreads();
    if (tid < 128) {
        float4 x0 = sred[tid + 128][0], x1 = sred[tid + 128][1];
        float4 y0 = sred[tid][0], y1 = sred[tid][1];
        y0.x += x0.x; y0.y += x0.y; y0.z += x0.z; y0.w += x0.w;
        y1.x += x1.x; y1.y += x1.y; y1.z += x1.z; y1.w += x1.w;
        sred[tid][0] = y0; sred[tid][1] = y1;
    }
    __syncthreads();
    if (tid < 64) {
        float4 x0 = sred[tid + 64][0], x1 = sred[tid + 64][1];
        float4 y0 = sred[tid][0], y1 = sred[tid][1];
        y0.x += x0.x; y0.y += x0.y; y0.z += x0.z; y0.w += x0.w;
        y1.x += x1.x; y1.y += x1.y; y1.z += x1.z; y1.w += x1.w;
        sred[tid][0] = y0; sred[tid][1] = y1;
    }
    __syncthreads();
    if (tid < 32) {
        float4 x0 = sred[tid + 32][0], x1 = sred[tid + 32][1];
        float4 y0 = sred[tid][0], y1 = sred[tid][1];
        y0.x += x0.x; y0.y += x0.y; y0.z += x0.z; y0.w += x0.w;
        y1.x += x1.x; y1.y += x1.y; y1.z += x1.z; y1.w += x1.w;
        __nv_bfloat162 p0 = __floats2bfloat162_rn(y0.x, y0.y);
        __nv_bfloat162 p1 = __floats2bfloat162_rn(y0.z, y0.w);
        __nv_bfloat162 p2 = __floats2bfloat162_rn(y1.x, y1.y);
        __nv_bfloat162 p3 = __floats2bfloat162_rn(y1.z, y1.w);
        uint4 pk;
        pk.x = *(uint32_t*)&p0; pk.y = *(uint32_t*)&p1;
        pk.z = *(uint32_t*)&p2; pk.w = *(uint32_t*)&p3;
        *(uint4*)(g_aggh + (size_t)n * CH + tid * 8) = pk;
    }
}

// ---------------- block reduction helper ----------------
__device__ __forceinline__ float blocksum256(float v, float* sh) {
    #pragma unroll
    for (int o = 16; o > 0; o >>= 1) v += __shfl_xor_sync(0xffffffffu, v, o);
    if ((threadIdx.x & 31) == 0) sh[threadIdx.x >> 5] = v;
    __syncthreads();
    float s = 0.f;
    #pragma unroll
    for (int i = 0; i < 8; i++) s += sh[i];
    __syncthreads();
    return s;
}

// ---------------- slots assembly + residual + LN1 ----------------
__global__ __launch_bounds__(256) void ln1_kernel(
    const float* __restrict__ query, const float* __restrict__ b_out,
    const float* __restrict__ gamma, const float* __restrict__ beta)
{
    __shared__ float sh[8];
    const int n = blockIdx.x, c = threadIdx.x;
    float m = g_cnt[n];
    float q = query[(size_t)n * CH + c];
    float s = m * (q + b_out[c]) + g_proj[(size_t)n * CH + c];
    float t = s / fmaxf(m, 1.0f) + q;
    float mu = blocksum256(t, sh) * (1.0f / CH);
    float d = t - mu;
    float var = blocksum256(d * d, sh) * (1.0f / CH);
    float xv = d * rsqrtf(var + 1e-5f) * gamma[c] + beta[c];
    g_x[(size_t)n * CH + c] = xv;
    g_x_h[(size_t)n * CH + c] = __float2bfloat16_rn(xv);
}

// ---------------- FFN residual + LN2 -> output ----------------
__global__ __launch_bounds__(256) void ln2_kernel(
    const float* __restrict__ gamma, const float* __restrict__ beta,
    float* __restrict__ out)
{
    __shared__ float sh[8];
    const int n = blockIdx.x, c = threadIdx.x;
    float t = g_x[(size_t)n * CH + c] + g_ffn2[(size_t)n * CH + c];
    float mu = blocksum256(t, sh) * (1.0f / CH);
    float d = t - mu;
    float var = blocksum256(d * d, sh) * (1.0f / CH);
    out[(size_t)n * CH + c] = d * rsqrtf(var + 1e-5f) * gamma[c] + beta[c];
}

// ---------------- host launcher ----------------
extern "C" void kernel_launch(void* const* d_in, const int* in_sizes, int n_in,
                              void* d_out, int out_size) {
    const float* query   = (const float*)d_in[0];
    const float* value   = (const float*)d_in[2];
    const float* refpts  = (const float*)d_in[3];
    const int*   bev     = (const int*)d_in[6];
    const float* W_value = (const float*)d_in[7];
    const float* b_value = (const float*)d_in[8];
    const float* W_off   = (const float*)d_in[9];
    const float* b_off   = (const float*)d_in[10];
    const float* W_attn  = (const float*)d_in[11];
    const float* b_attn  = (const float*)d_in[12];
    const float* W_out   = (const float*)d_in[13];
    const float* b_out   = (const float*)d_in[14];
    const float* ln1_g   = (const float*)d_in[15];
    const float* ln1_b   = (const float*)d_in[16];
    const float* W1      = (const float*)d_in[17];
    const float* b1      = (const float*)d_in[18];
    const float* W2      = (const float*)d_in[19];
    const float* b2      = (const float*)d_in[20];
    const float* ln2_g   = (const float*)d_in[21];
    const float* ln2_b   = (const float*)d_in[22];
    float* out = (float*)d_out;

    void *p_valh, *p_Wvalh, *p_vproj, *p_qh, *p_Wfh, *p_bf, *p_Wouth, *p_W1h, *p_W2h;
    void *p_fused, *p_aggh, *p_proj, *p_xh, *p_ffn1h, *p_ffn2;
    cudaGetSymbolAddress(&p_valh,   g_val_h);
    cudaGetSymbolAddress(&p_Wvalh,  g_Wval_h);
    cudaGetSymbolAddress(&p_vproj,  g_vproj);
    cudaGetSymbolAddress(&p_qh,     g_q_h);
    cudaGetSymbolAddress(&p_Wfh,    g_Wf_h);
    cudaGetSymbolAddress(&p_bf,     g_bf);
    cudaGetSymbolAddress(&p_Wouth,  g_Wout_h);
    cudaGetSymbolAddress(&p_W1h,    g_W1_h);
    cudaGetSymbolAddress(&p_W2h,    g_W2_h);
    cudaGetSymbolAddress(&p_fused,  g_fused);
    cudaGetSymbolAddress(&p_aggh,   g_aggh);
    cudaGetSymbolAddress(&p_proj,   g_proj);
    cudaGetSymbolAddress(&p_xh,     g_x_h);
    cudaGetSymbolAddress(&p_ffn1h,  g_ffn1h);
    cudaGetSymbolAddress(&p_ffn2,   g_ffn2);

    static cudaStream_t s2 = nullptr;
    static cudaEvent_t ev_fork = nullptr, ev_join = nullptr;
    if (s2 == nullptr) {
        cudaStreamCreateWithFlags(&s2, cudaStreamNonBlocking);
        cudaEventCreateWithFlags(&ev_fork, cudaEventDisableTiming);
        cudaEventCreateWithFlags(&ev_join, cudaEventDisableTiming);
    }

    // ---- fork: value/W_value conversion + wide vproj GEMM (bf16 out) on s2 ----
    cudaEventRecord(ev_fork, 0);
    cudaStreamWaitEvent(s2, ev_fork, 0);
    {
        int nconv = (MVAL * CH / 4 + CH * CH / 4 + 255) / 256;
        conv_val_kernel<<<nconv, 256, 0, s2>>>(value, W_value);
        hgemm_wide<1, __nv_bfloat16><<<dim3(MPAD / 128, CH / 128), 256, 0, s2>>>(
            (const __nv_bfloat16*)p_valh, (const __nv_bfloat16*)p_Wvalh,
            b_value, (__nv_bfloat16*)p_vproj, MPAD, CH, CH);
    }
    cudaEventRecord(ev_join, s2);

    // ---- main stream: prep + fused off/attn GEMM ----
    prep_kernel<<<2585, 256>>>(bev, query, W_off, W_attn, b_off, b_attn,
                               W_out, W1, W2);
    hgemm_bf16<1, float><<<dim3(NQ / 128, NFUS / 64), 256>>>(
        (const __nv_bfloat16*)p_qh, (const __nv_bfloat16*)p_Wfh,
        (const float*)p_bf, (float*)p_fused, NQ, NFUS, CH);

    // ---- join, then sampling ----
    cudaStreamWaitEvent(0, ev_join, 0);
    sample_kernel<<<NQ, 256>>>(refpts);

    // output projection: agg(bf16) @ W_out (bias folded into ln1)
    hgemm_bf16<0, float><<<dim3(NQ / 128, CH / 64), 256>>>(
        (const __nv_bfloat16*)p_aggh, (const __nv_bfloat16*)p_Wouth,
        nullptr, (float*)p_proj, NQ, CH, CH);

    // slots + residual + LN1
    ln1_kernel<<<NQ, 256>>>(query, b_out, ln1_g, ln1_b);

    // FFN up: relu(x @ W1 + b1) -> bf16 (wide 128x128 tile)
    hgemm_wide<2, __nv_bfloat16><<<dim3(NQ / 128, DFFN / 128), 256>>>(
        (const __nv_bfloat16*)p_xh, (const __nv_bfloat16*)p_W1h,
        b1, (__nv_bfloat16*)p_ffn1h, NQ, DFFN, CH);

    // FFN down: ffn1(bf16) @ W2 + b2
    hgemm_bf16<1, float><<<dim3(NQ / 128, CH / 64), 256>>>(
        (const __nv_bfloat16*)p_ffn1h, (const __nv_bfloat16*)p_W2h,
        b2, (float*)p_ffn2, NQ, CH, DFFN);

    // residual + LN2 -> out
    ln2_kernel<<<NQ, 256>>>(ln2_g, ln2_b, out);

    (void)in_sizes; (void)n_in; (void)out_size;
}